// round 10
// baseline (speedup 1.0000x reference)
#include <cuda_runtime.h>
#include <cuda_bf16.h>
#include <cuda_fp16.h>
#include <math.h>
#include <stdint.h>

#define Bn 4
#define Sn 2048
#define Dn 1024
#define NH 16
#define DH 64
#define Mrows (Bn*Sn)      // 8192
#define N3 (3*Dn)          // 3072

// Scratch (device globals: allocation-free per harness rules)
__device__ float g_qkv[(size_t)Mrows * N3];            // 96 MB
__device__ __half g_Ah[(size_t)Mrows * Dn];            // fp16(x) / fp16(attn out)
__device__ __half g_Wth[(size_t)N3 * Dn];              // W_qkv^T hi [N][K]
__device__ __half g_Wtl[(size_t)N3 * Dn];              // W_qkv^T lo
__device__ __half g_Woth[(size_t)Dn * Dn];             // W_o^T hi
__device__ __half g_Wotl[(size_t)Dn * Dn];
__device__ __nv_bfloat16 g_Qh[(size_t)Mrows * Dn];     // rmsnormed q split (bf16)
__device__ __nv_bfloat16 g_Ql[(size_t)Mrows * Dn];
__device__ __nv_bfloat16 g_Kh[(size_t)Mrows * Dn];
__device__ __nv_bfloat16 g_Kl[(size_t)Mrows * Dn];
__device__ __nv_bfloat16 g_Vth[(size_t)Mrows * Dn];    // V^T split: [(b*NH+h)*DH+d][s]
__device__ __nv_bfloat16 g_Vtl[(size_t)Mrows * Dn];

__device__ __forceinline__ void split_bf16(float x, __nv_bfloat16& h, __nv_bfloat16& l) {
    h = __float2bfloat16_rn(x);
    l = __float2bfloat16_rn(x - __bfloat162float(h));
}
__device__ __forceinline__ unsigned pack2(__nv_bfloat16 lo, __nv_bfloat16 hi) {
    __nv_bfloat162 p(lo, hi);
    return *(unsigned*)&p;
}
__device__ __forceinline__ void mma16816(float* c, const unsigned* a, const unsigned* b) {
    asm volatile(
        "mma.sync.aligned.m16n8k16.row.col.f32.bf16.bf16.f32 "
        "{%0,%1,%2,%3}, {%4,%5,%6,%7}, {%8,%9}, {%0,%1,%2,%3};"
        : "+f"(c[0]), "+f"(c[1]), "+f"(c[2]), "+f"(c[3])
        : "r"(a[0]), "r"(a[1]), "r"(a[2]), "r"(a[3]), "r"(b[0]), "r"(b[1]));
}
__device__ __forceinline__ void mma16816h(float* c, const unsigned* a, const unsigned* b) {
    asm volatile(
        "mma.sync.aligned.m16n8k16.row.col.f32.f16.f16.f32 "
        "{%0,%1,%2,%3}, {%4,%5,%6,%7}, {%8,%9}, {%0,%1,%2,%3};"
        : "+f"(c[0]), "+f"(c[1]), "+f"(c[2]), "+f"(c[3])
        : "r"(a[0]), "r"(a[1]), "r"(a[2]), "r"(a[3]), "r"(b[0]), "r"(b[1]));
}
__device__ __forceinline__ void cp16(unsigned smem_addr, const void* gptr) {
    asm volatile("cp.async.cg.shared.global [%0], [%1], 16;"
                 :: "r"(smem_addr), "l"(gptr));
}
__device__ __forceinline__ void ldsm4(unsigned& r0, unsigned& r1,
                                      unsigned& r2, unsigned& r3, unsigned addr) {
    asm volatile("ldmatrix.sync.aligned.m8n8.x4.shared.b16 {%0,%1,%2,%3}, [%4];"
                 : "=r"(r0), "=r"(r1), "=r"(r2), "=r"(r3) : "r"(addr));
}

// ---------------------------------------------------------------------------
// fp32 -> fp16 convert (for x)
// ---------------------------------------------------------------------------
__global__ void cvt_f16_kernel(const float* __restrict__ in,
                               __half* __restrict__ out, size_t n4) {
    size_t i = (size_t)blockIdx.x * blockDim.x + threadIdx.x;
    size_t stride = (size_t)gridDim.x * blockDim.x;
    for (; i < n4; i += stride) {
        float4 v = ((const float4*)in)[i];
        __half2 a(__float2half_rn(v.x), __float2half_rn(v.y));
        __half2 b(__float2half_rn(v.z), __float2half_rn(v.w));
        ((__half2*)out)[i * 2]     = a;
        ((__half2*)out)[i * 2 + 1] = b;
    }
}

// ---------------------------------------------------------------------------
// Transpose + fp16 hi/lo split: W[K][N] fp32 -> Wt hi/lo [N][K] fp16
// ---------------------------------------------------------------------------
__global__ void tsplit_f16_kernel(const float* __restrict__ W,
                                  __half* __restrict__ th,
                                  __half* __restrict__ tl, int K, int N) {
    __shared__ float t[32][33];
    int n0 = blockIdx.x * 32, k0 = blockIdx.y * 32;
    int tx = threadIdx.x, ty = threadIdx.y;           // (32, 8)
    #pragma unroll
    for (int i = ty; i < 32; i += 8)
        t[i][tx] = W[(size_t)(k0 + i) * N + n0 + tx];
    __syncthreads();
    #pragma unroll
    for (int i = ty; i < 32; i += 8) {
        float v = t[tx][i];
        __half h = __float2half_rn(v);
        __half l = __float2half_rn(v - __half2float(h));
        th[(size_t)(n0 + i) * K + k0 + tx] = h;
        tl[(size_t)(n0 + i) * K + k0 + tx] = l;
    }
}

// ---------------------------------------------------------------------------
// fp16x2 triple-buffered cp.async GEMM (W-side corrected) — round-9 verified.
// ---------------------------------------------------------------------------
#define BKK 32
#define PITCH 20                       // 16 data u32 + 4 pad (5x16B, coprime 8)
#define TILE_U32 (128 * PITCH)
#define TILEB (TILE_U32 * 4)
#define STAGE_U32 (3 * TILE_U32)       // A, Bh, Bl
#define GEMM_SMEM (3 * STAGE_U32 * 4)  // 3 stages = 92160 B

__global__ __launch_bounds__(256, 2)
void gemm_f16x2(const __half* __restrict__ A,
                const __half* __restrict__ Bth,
                const __half* __restrict__ Btl,
                const float* __restrict__ bias,
                float* __restrict__ C, int Nz, int Kz) {
    extern __shared__ unsigned sm[];

    const int tid  = threadIdx.x;
    const int lane = tid & 31;
    const int wid  = tid >> 5;
    const int wm   = wid >> 2;
    const int wn   = wid & 3;
    const int g    = lane >> 2;
    const int tig  = lane & 3;
    const int lane8 = lane & 7;
    const int lb3  = (lane >> 3) & 1;
    const int lb4  = (lane >> 4) & 1;

    const int rowBase = blockIdx.y * 128;
    const int colBase = blockIdx.x * 128;

    const int r0 = tid >> 2;           // cp.async row, +64 for it2=1
    const int c4 = tid & 3;            // 16B sector in row

    const unsigned smem_base = (unsigned)__cvta_generic_to_shared(sm);

    // ldmatrix per-lane address offsets (byte units, row pitch 80B)
    const unsigned a_off = (unsigned)((wm * 64 + lane8 + lb3 * 8) * 80 + lb4 * 16);
    const unsigned b_off = (unsigned)((wn * 32 + lane8 + lb4 * 8) * 80 + lb3 * 16);

    float acc[4][4][4];
    #pragma unroll
    for (int i = 0; i < 4; i++)
        #pragma unroll
        for (int j = 0; j < 4; j++)
            #pragma unroll
            for (int q = 0; q < 4; q++) acc[i][j][q] = 0.0f;

    const int NIT = Kz / BKK;

    auto load_stage = [&](int it, int buf) {
        const int k0 = it * BKK;
        const unsigned sbase = smem_base + buf * STAGE_U32 * 4;
        #pragma unroll
        for (int it2 = 0; it2 < 2; it2++) {
            int row = r0 + it2 * 64;
            unsigned soff = (unsigned)(row * PITCH + c4 * 4) * 4;
            const __half* gA  = A   + (size_t)(rowBase + row) * Kz + k0 + c4 * 8;
            const __half* gBh = Bth + (size_t)(colBase + row) * Kz + k0 + c4 * 8;
            const __half* gBl = Btl + (size_t)(colBase + row) * Kz + k0 + c4 * 8;
            cp16(sbase + soff, gA);
            cp16(sbase + TILEB + soff, gBh);
            cp16(sbase + 2 * TILEB + soff, gBl);
        }
        asm volatile("cp.async.commit_group;");
    };

    load_stage(0, 0);
    load_stage(1, 1);

    for (int it = 0; it < NIT; it++) {
        const int buf = it % 3;
        if (it + 2 < NIT) {
            load_stage(it + 2, (it + 2) % 3);
            asm volatile("cp.async.wait_group 2;");
        } else if (it + 1 < NIT) {
            asm volatile("cp.async.wait_group 1;");
        } else {
            asm volatile("cp.async.wait_group 0;");
        }
        __syncthreads();

        const unsigned stg = smem_base + buf * STAGE_U32 * 4;

        #pragma unroll
        for (int kk8 = 0; kk8 < 2; kk8++) {
            unsigned a[4][4], bhi[4][2], blo[4][2];
            #pragma unroll
            for (int mi = 0; mi < 4; mi++) {
                unsigned ad = stg + a_off + (unsigned)(mi * 16 * 80 + kk8 * 32);
                ldsm4(a[mi][0], a[mi][1], a[mi][2], a[mi][3], ad);
            }
            #pragma unroll
            for (int p = 0; p < 2; p++) {
                unsigned bd = stg + TILEB + b_off + (unsigned)(p * 16 * 80 + kk8 * 32);
                ldsm4(bhi[2*p][0], bhi[2*p][1], bhi[2*p+1][0], bhi[2*p+1][1], bd);
                ldsm4(blo[2*p][0], blo[2*p][1], blo[2*p+1][0], blo[2*p+1][1], bd + TILEB);
            }
            #pragma unroll
            for (int mi = 0; mi < 4; mi++)
                #pragma unroll
                for (int ni = 0; ni < 4; ni++) {
                    mma16816h(acc[mi][ni], a[mi], bhi[ni]);
                    mma16816h(acc[mi][ni], a[mi], blo[ni]);
                }
        }
        __syncthreads();
    }

    #pragma unroll
    for (int mi = 0; mi < 4; mi++) {
        int row0 = rowBase + wm * 64 + mi * 16 + g;
        int row1 = row0 + 8;
        #pragma unroll
        for (int ni = 0; ni < 4; ni++) {
            int col = colBase + wn * 32 + ni * 8 + tig * 2;
            float b0 = __ldg(&bias[col]);
            float b1 = __ldg(&bias[col + 1]);
            C[(size_t)row0 * Nz + col]     = acc[mi][ni][0] + b0;
            C[(size_t)row0 * Nz + col + 1] = acc[mi][ni][1] + b1;
            C[(size_t)row1 * Nz + col]     = acc[mi][ni][2] + b0;
            C[(size_t)row1 * Nz + col + 1] = acc[mi][ni][3] + b1;
        }
    }
}

// ---------------------------------------------------------------------------
// Fused RMSNorm + bf16 hi/lo split: g_qkv q/k sections -> g_Qh/Ql/Kh/Kl.
// ---------------------------------------------------------------------------
__global__ void rmsnorm_split_kernel(const float* __restrict__ wq,
                                     const float* __restrict__ wk) {
    int gw = (blockIdx.x * blockDim.x + threadIdx.x) >> 5;
    int lane = threadIdx.x & 31;
    int which = gw & 1;
    int head = (gw >> 1) & 15;
    int row = gw >> 5;
    if (row >= Mrows) return;

    const float* p = g_qkv + (size_t)row * N3 + which * Dn + head * DH;
    float2 v = ((const float2*)p)[lane];
    float ss = v.x * v.x + v.y * v.y;
    #pragma unroll
    for (int o = 16; o; o >>= 1) ss += __shfl_xor_sync(0xffffffffu, ss, o);
    float inv = rsqrtf(ss * (1.0f / DH) + 1e-6f);
    const float* w = which ? wk : wq;
    float2 wv = ((const float2*)w)[lane];
    float a0 = v.x * inv * wv.x;
    float a1 = v.y * inv * wv.y;

    __nv_bfloat16 h0, l0, h1, l1;
    split_bf16(a0, h0, l0);
    split_bf16(a1, h1, l1);
    size_t off = (size_t)row * Dn + head * DH;
    __nv_bfloat16* dh = (which ? g_Kh : g_Qh) + off;
    __nv_bfloat16* dl = (which ? g_Kl : g_Ql) + off;
    ((__nv_bfloat162*)dh)[lane] = __nv_bfloat162(h0, h1);
    ((__nv_bfloat162*)dl)[lane] = __nv_bfloat162(l0, l1);
}

// ---------------------------------------------------------------------------
// V transpose + split: g_qkv v section [b,s][h,d] -> g_Vth/Vtl [(b,h,d)][s]
// ---------------------------------------------------------------------------
__global__ void vsplit_kernel() {
    __shared__ float t[64][65];
    int s0 = blockIdx.x * 64;
    int h = blockIdx.y, b = blockIdx.z;
    int tid = threadIdx.x;
    #pragma unroll
    for (int it = 0; it < 16; it++) {
        int idx = tid + it * 256;
        int sr = idx >> 6, d = idx & 63;
        t[sr][d] = g_qkv[((size_t)b * Sn + s0 + sr) * N3 + 2 * Dn + h * DH + d];
    }
    __syncthreads();
    #pragma unroll
    for (int it = 0; it < 16; it++) {
        int idx = tid + it * 256;
        int d = idx >> 6, sc = idx & 63;
        float v = t[sc][d];
        __nv_bfloat16 hh, ll;
        split_bf16(v, hh, ll);
        size_t off = ((size_t)(b * NH + h) * DH + d) * Sn + s0 + sc;
        g_Vth[off] = hh;
        g_Vtl[off] = ll;
    }
}

// ---------------------------------------------------------------------------
// Flash attention, bf16x3 mma.sync + ldmatrix. 128-row q tile per CTA
// (256 thr = 8 warps x 16 rows) — halves K/V tile traffic vs 64-row tiles.
// Per-row arithmetic identical to the 64-row version (extra diagonal tiles
// for upper-half rows are fully masked -> exact no-ops).
// ---------------------------------------------------------------------------
#define AP 36
#define ATILE (64 * AP)                // K/V tile u32 (2304)
#define ATB (ATILE * 4)                // 9216 B
#define QTILE (128 * AP)               // Q tile u32 (4608)
#define QTB (QTILE * 4)                // 18432 B
#define KOFF (2 * QTILE)               // u32 offset of Kh
#define ATTN_SMEM ((2 * QTILE + 4 * ATILE) * 4)   // 73728 B

__global__ __launch_bounds__(256, 2) void attn_mma_kernel() {
    extern __shared__ unsigned smu[];

    const int tid  = threadIdx.x;
    const int lane = tid & 31;
    const int w    = tid >> 5;         // 0..7 -> 16 q rows each
    const int g    = lane >> 2;
    const int tig  = lane & 3;
    const int lane8 = lane & 7;
    const int lb3  = (lane >> 3) & 1;
    const int lb4  = (lane >> 4) & 1;

    const int qt = gridDim.x - 1 - blockIdx.x;   // 0..15 (big tiles first)
    const int h  = blockIdx.y;
    const int b  = blockIdx.z;

    const size_t rowQ0 = (size_t)b * Sn + qt * 128;
    const size_t qk_off = h * DH;
    const size_t v_row0 = (size_t)(b * NH + h) * DH;

    const unsigned smu_b = (unsigned)__cvta_generic_to_shared(smu);
    const int m0r = w * 16;
    const unsigned q_loff = (unsigned)((m0r + lane8 + lb3 * 8) * 144 + lb4 * 16);
    const unsigned n_loff = (unsigned)((lane8 + lb4 * 8) * 144 + lb3 * 16);

    // Q load: 2 tiles (hi/lo) x 128 rows x 8 uint4 = 2048 / 256 thr = 8 each
    #pragma unroll
    for (int it = 0; it < 8; it++) {
        int idx = tid + it * 256;
        int t = idx >> 10, rem = idx & 1023;
        int r = rem >> 3, q4 = rem & 7;
        const uint4* src = (const uint4*)((t ? g_Ql : g_Qh) + (rowQ0 + r) * Dn + qk_off);
        ((uint4*)(smu + t * QTILE + r * AP))[q4] = src[q4];
    }

    float o[8][4];
    #pragma unroll
    for (int ni = 0; ni < 8; ni++)
        #pragma unroll
        for (int c = 0; c < 4; c++) o[ni][c] = 0.0f;
    float m0 = -INFINITY, m1 = -INFINITY, l0 = 0.0f, l1 = 0.0f;

    __syncthreads();

    const int ktmax = 2 * qt + 1;
    for (int kt = 0; kt <= ktmax; kt++) {
        const size_t rowK0 = (size_t)b * Sn + kt * 64;
        // K/V load: 4 tiles x 64 rows x 8 uint4 = 2048 / 256 = 8 each
        #pragma unroll
        for (int it = 0; it < 8; it++) {
            int t = it >> 1;
            int r = (tid >> 3) + (it & 1) * 32;     // 0..63
            int q4 = tid & 7;
            const uint4* src;
            if (t == 0)      src = (const uint4*)(g_Kh  + (rowK0 + r) * Dn + qk_off);
            else if (t == 1) src = (const uint4*)(g_Kl  + (rowK0 + r) * Dn + qk_off);
            else if (t == 2) src = (const uint4*)(g_Vth + (v_row0 + r) * Sn + kt * 64);
            else             src = (const uint4*)(g_Vtl + (v_row0 + r) * Sn + kt * 64);
            ((uint4*)(smu + KOFF + t * ATILE + r * AP))[q4] = src[q4];
        }
        __syncthreads();

        // ---- S = Q @ K^T (bf16x3) ----
        float s[8][4];
        #pragma unroll
        for (int ni = 0; ni < 8; ni++)
            #pragma unroll
            for (int c = 0; c < 4; c++) s[ni][c] = 0.0f;

        #pragma unroll
        for (int kk = 0; kk < 4; kk++) {
            unsigned ah[4], al[4];
            ldsm4(ah[0], ah[1], ah[2], ah[3], smu_b + q_loff + kk * 32);
            ldsm4(al[0], al[1], al[2], al[3], smu_b + QTB + q_loff + kk * 32);
            #pragma unroll
            for (int p = 0; p < 4; p++) {
                unsigned bh[4], bl[4];
                unsigned kd = smu_b + KOFF * 4 + n_loff + (unsigned)(p * 16 * 144 + kk * 32);
                ldsm4(bh[0], bh[1], bh[2], bh[3], kd);
                ldsm4(bl[0], bl[1], bl[2], bl[3], kd + ATB);
                mma16816(s[2*p],   ah, bh);
                mma16816(s[2*p],   ah, bl);
                mma16816(s[2*p],   al, bh);
                mma16816(s[2*p+1], ah, bh + 2);
                mma16816(s[2*p+1], ah, bl + 2);
                mma16816(s[2*p+1], al, bh + 2);
            }
        }

        // ---- causal mask (only the two diagonal-band k tiles) ----
        if (kt >= 2 * qt) {
            int cbase = kt * 64 - qt * 128;         // 0 or 64
            #pragma unroll
            for (int ni = 0; ni < 8; ni++) {
                int col = cbase + ni * 8 + 2 * tig;
                int r0 = m0r + g, r1 = r0 + 8;
                if (col > r0)     s[ni][0] = -INFINITY;
                if (col + 1 > r0) s[ni][1] = -INFINITY;
                if (col > r1)     s[ni][2] = -INFINITY;
                if (col + 1 > r1) s[ni][3] = -INFINITY;
            }
        }

        // ---- online softmax ----
        float rm0 = -INFINITY, rm1 = -INFINITY;
        #pragma unroll
        for (int ni = 0; ni < 8; ni++) {
            rm0 = fmaxf(rm0, fmaxf(s[ni][0], s[ni][1]));
            rm1 = fmaxf(rm1, fmaxf(s[ni][2], s[ni][3]));
        }
        rm0 = fmaxf(rm0, __shfl_xor_sync(0xffffffffu, rm0, 1));
        rm0 = fmaxf(rm0, __shfl_xor_sync(0xffffffffu, rm0, 2));
        rm1 = fmaxf(rm1, __shfl_xor_sync(0xffffffffu, rm1, 1));
        rm1 = fmaxf(rm1, __shfl_xor_sync(0xffffffffu, rm1, 2));
        float mn0 = fmaxf(m0, rm0), mn1 = fmaxf(m1, rm1);

        float rs0 = 0.0f, rs1 = 0.0f;
        #pragma unroll
        for (int ni = 0; ni < 8; ni++) {
            s[ni][0] = __expf(s[ni][0] - mn0);
            s[ni][1] = __expf(s[ni][1] - mn0);
            s[ni][2] = __expf(s[ni][2] - mn1);
            s[ni][3] = __expf(s[ni][3] - mn1);
            rs0 += s[ni][0] + s[ni][1];
            rs1 += s[ni][2] + s[ni][3];
        }
        rs0 += __shfl_xor_sync(0xffffffffu, rs0, 1);
        rs0 += __shfl_xor_sync(0xffffffffu, rs0, 2);
        rs1 += __shfl_xor_sync(0xffffffffu, rs1, 1);
        rs1 += __shfl_xor_sync(0xffffffffu, rs1, 2);

        float al0 = __expf(m0 - mn0), al1 = __expf(m1 - mn1);
        l0 = l0 * al0 + rs0;
        l1 = l1 * al1 + rs1;
        m0 = mn0; m1 = mn1;
        #pragma unroll
        for (int ni = 0; ni < 8; ni++) {
            o[ni][0] *= al0; o[ni][1] *= al0;
            o[ni][2] *= al1; o[ni][3] *= al1;
        }

        // ---- O += P @ V (bf16x3, P split in registers) ----
        #pragma unroll
        for (int kk = 0; kk < 4; kk++) {
            unsigned pah[4], pal[4];
            {
                __nv_bfloat16 h00,l00,h01,l01,h10,l10,h11,l11;
                split_bf16(s[2*kk][0], h00, l00);
                split_bf16(s[2*kk][1], h01, l01);
                split_bf16(s[2*kk][2], h10, l10);
                split_bf16(s[2*kk][3], h11, l11);
                pah[0] = pack2(h00, h01); pal[0] = pack2(l00, l01);
                pah[1] = pack2(h10, h11); pal[1] = pack2(l10, l11);
                split_bf16(s[2*kk+1][0], h00, l00);
                split_bf16(s[2*kk+1][1], h01, l01);
                split_bf16(s[2*kk+1][2], h10, l10);
                split_bf16(s[2*kk+1][3], h11, l11);
                pah[2] = pack2(h00, h01); pal[2] = pack2(l00, l01);
                pah[3] = pack2(h10, h11); pal[3] = pack2(l10, l11);
            }
            #pragma unroll
            for (int p = 0; p < 4; p++) {
                unsigned vh[4], vl[4];
                unsigned vd = smu_b + (KOFF + 2 * ATILE) * 4 + n_loff
                              + (unsigned)(p * 16 * 144 + kk * 32);
                ldsm4(vh[0], vh[1], vh[2], vh[3], vd);
                ldsm4(vl[0], vl[1], vl[2], vl[3], vd + ATB);
                mma16816(o[2*p],   pah, vh);
                mma16816(o[2*p],   pah, vl);
                mma16816(o[2*p],   pal, vh);
                mma16816(o[2*p+1], pah, vh + 2);
                mma16816(o[2*p+1], pah, vl + 2);
                mma16816(o[2*p+1], pal, vh + 2);
            }
        }
        __syncthreads();
    }

    // finalize: z = O / l -> fp16 into g_Ah (O-proj A operand)
    float inv0 = 1.0f / l0, inv1 = 1.0f / l1;
    size_t row0 = rowQ0 + m0r + g;
    size_t row1 = row0 + 8;
    #pragma unroll
    for (int ni = 0; ni < 8; ni++) {
        int col = h * DH + ni * 8 + 2 * tig;
        __half2 z0(__float2half_rn(o[ni][0] * inv0), __float2half_rn(o[ni][1] * inv0));
        __half2 z1(__float2half_rn(o[ni][2] * inv1), __float2half_rn(o[ni][3] * inv1));
        *(__half2*)&g_Ah[row0 * Dn + col] = z0;
        *(__half2*)&g_Ah[row1 * Dn + col] = z1;
    }
}

// ---------------------------------------------------------------------------
extern "C" void kernel_launch(void* const* d_in, const int* in_sizes, int n_in,
                              void* d_out, int out_size) {
    const float* x     = (const float*)d_in[0];
    const float* W_qkv = (const float*)d_in[2];
    const float* b_qkv = (const float*)d_in[3];
    const float* W_o   = (const float*)d_in[4];
    const float* b_o   = (const float*)d_in[5];
    const float* wq    = (const float*)d_in[6];
    const float* wk    = (const float*)d_in[7];
    float* out = (float*)d_out;

    void *qkv_ptr, *ah, *wth, *wtl, *woth, *wotl;
    cudaGetSymbolAddress(&qkv_ptr, g_qkv);
    cudaGetSymbolAddress(&ah, g_Ah);
    cudaGetSymbolAddress(&wth, g_Wth);
    cudaGetSymbolAddress(&wtl, g_Wtl);
    cudaGetSymbolAddress(&woth, g_Woth);
    cudaGetSymbolAddress(&wotl, g_Wotl);

    cudaFuncSetAttribute(gemm_f16x2,
                         cudaFuncAttributeMaxDynamicSharedMemorySize, GEMM_SMEM);
    cudaFuncSetAttribute(attn_mma_kernel,
                         cudaFuncAttributeMaxDynamicSharedMemorySize, ATTN_SMEM);

    // 0) Preprocessing: x -> fp16; transpose+split weights (fp16 hi/lo)
    cvt_f16_kernel<<<1024, 256>>>(x, (__half*)ah, (size_t)Mrows * Dn / 4);
    {
        dim3 grid(N3 / 32, Dn / 32);
        tsplit_f16_kernel<<<grid, dim3(32, 8)>>>(W_qkv, (__half*)wth,
                                                 (__half*)wtl, Dn, N3);
    }
    {
        dim3 grid(Dn / 32, Dn / 32);
        tsplit_f16_kernel<<<grid, dim3(32, 8)>>>(W_o, (__half*)woth,
                                                 (__half*)wotl, Dn, Dn);
    }

    // 1) QKV GEMM (fp16x2)
    {
        dim3 grid(N3 / 128, Mrows / 128);
        gemm_f16x2<<<grid, 256, GEMM_SMEM>>>(
            (const __half*)ah, (const __half*)wth, (const __half*)wtl,
            b_qkv, (float*)qkv_ptr, N3, Dn);
    }

    // 2) RMSNorm + split q,k (bf16); transpose-split v (bf16)
    {
        int total_warps = Mrows * NH * 2;
        int blocks = (total_warps * 32) / 256;
        rmsnorm_split_kernel<<<blocks, 256>>>(wq, wk);
    }
    {
        dim3 grid(Sn / 64, NH, Bn);
        vsplit_kernel<<<grid, 256>>>();
    }

    // 3) Flash attention (128-row q tiles) — writes fp16 z into g_Ah
    {
        dim3 grid(Sn / 128, NH, Bn);
        attn_mma_kernel<<<grid, 256, ATTN_SMEM>>>();
    }

    // 4) Output projection (fp16x2)
    {
        dim3 grid(Dn / 128, Mrows / 128);
        gemm_f16x2<<<grid, 256, GEMM_SMEM>>>(
            (const __half*)ah, (const __half*)woth, (const __half*)wotl,
            b_o, out, Dn, Dn);
    }
}

// round 12
// speedup vs baseline: 1.0205x; 1.0205x over previous
#include <cuda_runtime.h>
#include <cuda_bf16.h>
#include <cuda_fp16.h>
#include <math.h>
#include <stdint.h>

#define Bn 4
#define Sn 2048
#define Dn 1024
#define NH 16
#define DH 64
#define Mrows (Bn*Sn)      // 8192
#define N3 (3*Dn)          // 3072

// Scratch (device globals: allocation-free per harness rules)
__device__ __half g_Ah[(size_t)Mrows * Dn];            // fp16(x) / fp16(attn out)
__device__ __half g_Wth[(size_t)N3 * Dn];              // W_qkv^T hi [N][K]
__device__ __half g_Wtl[(size_t)N3 * Dn];              // W_qkv^T lo
__device__ __half g_Woth[(size_t)Dn * Dn];             // W_o^T hi
__device__ __half g_Wotl[(size_t)Dn * Dn];
__device__ __nv_bfloat16 g_Qh[(size_t)Mrows * Dn];     // rmsnormed q split (bf16)
__device__ __nv_bfloat16 g_Ql[(size_t)Mrows * Dn];
__device__ __nv_bfloat16 g_Kh[(size_t)Mrows * Dn];
__device__ __nv_bfloat16 g_Kl[(size_t)Mrows * Dn];
__device__ __nv_bfloat16 g_Vth[(size_t)Mrows * Dn];    // V^T split: [(b*NH+h)*DH+d][s]
__device__ __nv_bfloat16 g_Vtl[(size_t)Mrows * Dn];

__device__ __forceinline__ void split_bf16(float x, __nv_bfloat16& h, __nv_bfloat16& l) {
    h = __float2bfloat16_rn(x);
    l = __float2bfloat16_rn(x - __bfloat162float(h));
}
__device__ __forceinline__ unsigned pack2(__nv_bfloat16 lo, __nv_bfloat16 hi) {
    __nv_bfloat162 p(lo, hi);
    return *(unsigned*)&p;
}
__device__ __forceinline__ void mma16816(float* c, const unsigned* a, const unsigned* b) {
    asm volatile(
        "mma.sync.aligned.m16n8k16.row.col.f32.bf16.bf16.f32 "
        "{%0,%1,%2,%3}, {%4,%5,%6,%7}, {%8,%9}, {%0,%1,%2,%3};"
        : "+f"(c[0]), "+f"(c[1]), "+f"(c[2]), "+f"(c[3])
        : "r"(a[0]), "r"(a[1]), "r"(a[2]), "r"(a[3]), "r"(b[0]), "r"(b[1]));
}
__device__ __forceinline__ void mma16816h(float* c, const unsigned* a, const unsigned* b) {
    asm volatile(
        "mma.sync.aligned.m16n8k16.row.col.f32.f16.f16.f32 "
        "{%0,%1,%2,%3}, {%4,%5,%6,%7}, {%8,%9}, {%0,%1,%2,%3};"
        : "+f"(c[0]), "+f"(c[1]), "+f"(c[2]), "+f"(c[3])
        : "r"(a[0]), "r"(a[1]), "r"(a[2]), "r"(a[3]), "r"(b[0]), "r"(b[1]));
}
__device__ __forceinline__ void cp16(unsigned smem_addr, const void* gptr) {
    asm volatile("cp.async.cg.shared.global [%0], [%1], 16;"
                 :: "r"(smem_addr), "l"(gptr));
}
__device__ __forceinline__ void ldsm4(unsigned& r0, unsigned& r1,
                                      unsigned& r2, unsigned& r3, unsigned addr) {
    asm volatile("ldmatrix.sync.aligned.m8n8.x4.shared.b16 {%0,%1,%2,%3}, [%4];"
                 : "=r"(r0), "=r"(r1), "=r"(r2), "=r"(r3) : "r"(addr));
}

// ---------------------------------------------------------------------------
// fp32 -> fp16 convert (for x)
// ---------------------------------------------------------------------------
__global__ void cvt_f16_kernel(const float* __restrict__ in,
                               __half* __restrict__ out, size_t n4) {
    size_t i = (size_t)blockIdx.x * blockDim.x + threadIdx.x;
    size_t stride = (size_t)gridDim.x * blockDim.x;
    for (; i < n4; i += stride) {
        float4 v = ((const float4*)in)[i];
        __half2 a(__float2half_rn(v.x), __float2half_rn(v.y));
        __half2 b(__float2half_rn(v.z), __float2half_rn(v.w));
        ((__half2*)out)[i * 2]     = a;
        ((__half2*)out)[i * 2 + 1] = b;
    }
}

// ---------------------------------------------------------------------------
// Transpose + fp16 hi/lo split: W[K][N] fp32 -> Wt hi/lo [N][K] fp16
// ---------------------------------------------------------------------------
__global__ void tsplit_f16_kernel(const float* __restrict__ W,
                                  __half* __restrict__ th,
                                  __half* __restrict__ tl, int K, int N) {
    __shared__ float t[32][33];
    int n0 = blockIdx.x * 32, k0 = blockIdx.y * 32;
    int tx = threadIdx.x, ty = threadIdx.y;           // (32, 8)
    #pragma unroll
    for (int i = ty; i < 32; i += 8)
        t[i][tx] = W[(size_t)(k0 + i) * N + n0 + tx];
    __syncthreads();
    #pragma unroll
    for (int i = ty; i < 32; i += 8) {
        float v = t[tx][i];
        __half h = __float2half_rn(v);
        __half l = __float2half_rn(v - __half2float(h));
        th[(size_t)(n0 + i) * K + k0 + tx] = h;
        tl[(size_t)(n0 + i) * K + k0 + tx] = l;
    }
}

// ---------------------------------------------------------------------------
// fp16x2 triple-buffered cp.async GEMM (round-9 verified mainloop).
// FUSED=1 (QKV): epilogue does rmsnorm+bf16-split for q/k sections and
// transpose+bf16-split for the v section (no fp32 C written at all).
// FUSED=0 (O-proj): plain bias + fp32 store to C.
// ---------------------------------------------------------------------------
#define BKK 32
#define PITCH 20                       // 16 data u32 + 4 pad (5x16B, coprime 8)
#define TILE_U32 (128 * PITCH)
#define TILEB (TILE_U32 * 4)
#define STAGE_U32 (3 * TILE_U32)       // A, Bh, Bl
#define GEMM_SMEM (3 * STAGE_U32 * 4)  // 3 stages = 92160 B (>= 128*129*4 transpose)

template<int FUSED>
__global__ __launch_bounds__(256, 2)
void gemm_f16x2(const __half* __restrict__ A,
                const __half* __restrict__ Bth,
                const __half* __restrict__ Btl,
                const float* __restrict__ bias,
                float* __restrict__ C,
                const float* __restrict__ wq,
                const float* __restrict__ wk,
                int Nz, int Kz) {
    extern __shared__ unsigned sm[];

    const int tid  = threadIdx.x;
    const int lane = tid & 31;
    const int wid  = tid >> 5;
    const int wm   = wid >> 2;
    const int wn   = wid & 3;
    const int g    = lane >> 2;
    const int tig  = lane & 3;
    const int lane8 = lane & 7;
    const int lb3  = (lane >> 3) & 1;
    const int lb4  = (lane >> 4) & 1;

    const int rowBase = blockIdx.y * 128;
    const int colBase = blockIdx.x * 128;

    const int r0 = tid >> 2;           // cp.async row, +64 for it2=1
    const int c4 = tid & 3;            // 16B sector in row

    const unsigned smem_base = (unsigned)__cvta_generic_to_shared(sm);

    const unsigned a_off = (unsigned)((wm * 64 + lane8 + lb3 * 8) * 80 + lb4 * 16);
    const unsigned b_off = (unsigned)((wn * 32 + lane8 + lb4 * 8) * 80 + lb3 * 16);

    float acc[4][4][4];
    #pragma unroll
    for (int i = 0; i < 4; i++)
        #pragma unroll
        for (int j = 0; j < 4; j++)
            #pragma unroll
            for (int q = 0; q < 4; q++) acc[i][j][q] = 0.0f;

    const int NIT = Kz / BKK;

    auto load_stage = [&](int it, int buf) {
        const int k0 = it * BKK;
        const unsigned sbase = smem_base + buf * STAGE_U32 * 4;
        #pragma unroll
        for (int it2 = 0; it2 < 2; it2++) {
            int row = r0 + it2 * 64;
            unsigned soff = (unsigned)(row * PITCH + c4 * 4) * 4;
            const __half* gA  = A   + (size_t)(rowBase + row) * Kz + k0 + c4 * 8;
            const __half* gBh = Bth + (size_t)(colBase + row) * Kz + k0 + c4 * 8;
            const __half* gBl = Btl + (size_t)(colBase + row) * Kz + k0 + c4 * 8;
            cp16(sbase + soff, gA);
            cp16(sbase + TILEB + soff, gBh);
            cp16(sbase + 2 * TILEB + soff, gBl);
        }
        asm volatile("cp.async.commit_group;");
    };

    load_stage(0, 0);
    load_stage(1, 1);

    for (int it = 0; it < NIT; it++) {
        const int buf = it % 3;
        if (it + 2 < NIT) {
            load_stage(it + 2, (it + 2) % 3);
            asm volatile("cp.async.wait_group 2;");
        } else if (it + 1 < NIT) {
            asm volatile("cp.async.wait_group 1;");
        } else {
            asm volatile("cp.async.wait_group 0;");
        }
        __syncthreads();

        const unsigned stg = smem_base + buf * STAGE_U32 * 4;

        #pragma unroll
        for (int kk8 = 0; kk8 < 2; kk8++) {
            unsigned a[4][4], bhi[4][2], blo[4][2];
            #pragma unroll
            for (int mi = 0; mi < 4; mi++) {
                unsigned ad = stg + a_off + (unsigned)(mi * 16 * 80 + kk8 * 32);
                ldsm4(a[mi][0], a[mi][1], a[mi][2], a[mi][3], ad);
            }
            #pragma unroll
            for (int p = 0; p < 2; p++) {
                unsigned bd = stg + TILEB + b_off + (unsigned)(p * 16 * 80 + kk8 * 32);
                ldsm4(bhi[2*p][0], bhi[2*p][1], bhi[2*p+1][0], bhi[2*p+1][1], bd);
                ldsm4(blo[2*p][0], blo[2*p][1], blo[2*p+1][0], blo[2*p+1][1], bd + TILEB);
            }
            #pragma unroll
            for (int mi = 0; mi < 4; mi++)
                #pragma unroll
                for (int ni = 0; ni < 4; ni++) {
                    mma16816h(acc[mi][ni], a[mi], bhi[ni]);
                    mma16816h(acc[mi][ni], a[mi], blo[ni]);
                }
        }
        __syncthreads();
    }
    // NOTE: final __syncthreads() above means all smem stage reads are done;
    // the epilogue may reuse sm[].

    if (!FUSED) {
        // Plain epilogue: bias + fp32 store
        #pragma unroll
        for (int mi = 0; mi < 4; mi++) {
            int row0 = rowBase + wm * 64 + mi * 16 + g;
            int row1 = row0 + 8;
            #pragma unroll
            for (int ni = 0; ni < 4; ni++) {
                int col = colBase + wn * 32 + ni * 8 + tig * 2;
                float b0 = __ldg(&bias[col]);
                float b1 = __ldg(&bias[col + 1]);
                C[(size_t)row0 * Nz + col]     = acc[mi][ni][0] + b0;
                C[(size_t)row0 * Nz + col + 1] = acc[mi][ni][1] + b1;
                C[(size_t)row1 * Nz + col]     = acc[mi][ni][2] + b0;
                C[(size_t)row1 * Nz + col + 1] = acc[mi][ni][3] + b1;
            }
        }
        return;
    }

    // ----- FUSED epilogue (QKV) -----
    // Add bias first.
    #pragma unroll
    for (int ni = 0; ni < 4; ni++) {
        int col = colBase + wn * 32 + ni * 8 + tig * 2;
        float b0 = __ldg(&bias[col]);
        float b1 = __ldg(&bias[col + 1]);
        #pragma unroll
        for (int mi = 0; mi < 4; mi++) {
            acc[mi][ni][0] += b0; acc[mi][ni][1] += b1;
            acc[mi][ni][2] += b0; acc[mi][ni][3] += b1;
        }
    }

    const int sec = colBase >> 10;         // 0=q, 1=k, 2=v
    const int cb  = colBase & 1023;
    const int bb  = rowBase >> 11;         // batch (Sn = 2048)
    const int s0row = rowBase & 2047;

    if (sec < 2) {
        // --- RMSNorm + bf16 split for q/k ---
        float* red = (float*)sm;           // [4 warpsN][128 rows]
        #pragma unroll
        for (int mi = 0; mi < 4; mi++) {
            float l0 = 0.0f, l1 = 0.0f;
            #pragma unroll
            for (int ni = 0; ni < 4; ni++) {
                l0 += acc[mi][ni][0] * acc[mi][ni][0] + acc[mi][ni][1] * acc[mi][ni][1];
                l1 += acc[mi][ni][2] * acc[mi][ni][2] + acc[mi][ni][3] * acc[mi][ni][3];
            }
            l0 += __shfl_xor_sync(0xffffffffu, l0, 1);
            l0 += __shfl_xor_sync(0xffffffffu, l0, 2);
            l1 += __shfl_xor_sync(0xffffffffu, l1, 1);
            l1 += __shfl_xor_sync(0xffffffffu, l1, 2);
            if (tig == 0) {
                int lr = wm * 64 + mi * 16 + g;
                red[wn * 128 + lr]     = l0;
                red[wn * 128 + lr + 8] = l1;
            }
        }
        __syncthreads();

        const float* wv = sec ? wk : wq;
        __nv_bfloat16* dh = sec ? g_Kh : g_Qh;
        __nv_bfloat16* dl = sec ? g_Kl : g_Ql;
        const int head = (cb >> 6) + (wn >> 1);

        #pragma unroll
        for (int mi = 0; mi < 4; mi++) {
            int lr = wm * 64 + mi * 16 + g;
            float ssq0 = red[wn * 128 + lr]     + red[(wn ^ 1) * 128 + lr];
            float ssq1 = red[wn * 128 + lr + 8] + red[(wn ^ 1) * 128 + lr + 8];
            float inv0 = rsqrtf(ssq0 * (1.0f / DH) + 1e-6f);
            float inv1 = rsqrtf(ssq1 * (1.0f / DH) + 1e-6f);
            size_t row0 = (size_t)(rowBase + lr);
            size_t row1 = row0 + 8;
            #pragma unroll
            for (int ni = 0; ni < 4; ni++) {
                int ic = (wn & 1) * 32 + ni * 8 + tig * 2;
                float wf0 = __ldg(&wv[ic]);
                float wf1 = __ldg(&wv[ic + 1]);
                size_t o0 = row0 * Dn + head * 64 + ic;
                size_t o1 = row1 * Dn + head * 64 + ic;
                __nv_bfloat16 h0, lo0, h1, lo1;
                split_bf16(acc[mi][ni][0] * inv0 * wf0, h0, lo0);
                split_bf16(acc[mi][ni][1] * inv0 * wf1, h1, lo1);
                *(unsigned*)&dh[o0] = pack2(h0, h1);
                *(unsigned*)&dl[o0] = pack2(lo0, lo1);
                split_bf16(acc[mi][ni][2] * inv1 * wf0, h0, lo0);
                split_bf16(acc[mi][ni][3] * inv1 * wf1, h1, lo1);
                *(unsigned*)&dh[o1] = pack2(h0, h1);
                *(unsigned*)&dl[o1] = pack2(lo0, lo1);
            }
        }
    } else {
        // --- V: transpose via smem, bf16 split, write [d][s] ---
        float (*vt)[129] = (float(*)[129])sm;   // 128 x 129 fp32 = 66048 B
        #pragma unroll
        for (int mi = 0; mi < 4; mi++) {
            int lr0 = wm * 64 + mi * 16 + g;
            #pragma unroll
            for (int ni = 0; ni < 4; ni++) {
                int lc = wn * 32 + ni * 8 + tig * 2;
                vt[lr0][lc]     = acc[mi][ni][0];
                vt[lr0][lc + 1] = acc[mi][ni][1];
                vt[lr0 + 8][lc]     = acc[mi][ni][2];
                vt[lr0 + 8][lc + 1] = acc[mi][ni][3];
            }
        }
        __syncthreads();

        int d  = tid >> 1;               // 0..127
        int sh = (tid & 1) * 64;         // s half
        int hg = (cb >> 6) + (d >> 6);   // global head
        int dl_ = d & 63;
        size_t base = ((size_t)(bb * NH + hg) * DH + dl_) * Sn + s0row + sh;
        #pragma unroll
        for (int i = 0; i < 64; i += 2) {
            float v0 = vt[sh + i][d];
            float v1 = vt[sh + i + 1][d];
            __nv_bfloat16 h0, l0, h1, l1;
            split_bf16(v0, h0, l0);
            split_bf16(v1, h1, l1);
            *(unsigned*)&g_Vth[base + i] = pack2(h0, h1);
            *(unsigned*)&g_Vtl[base + i] = pack2(l0, l1);
        }
    }
}

// ---------------------------------------------------------------------------
// Flash attention, bf16x3 mma.sync + ldmatrix, 64-row q tiles
// (round-9 verified, 838us config). Epilogue writes fp16 z into g_Ah.
// ---------------------------------------------------------------------------
#define AP 36
#define ATILE (64 * AP)
#define ATB (ATILE * 4)                // tile bytes 9216
#define ATTN_SMEM (6 * ATILE * 4)      // 55296 B

__global__ __launch_bounds__(128) void attn_mma_kernel() {
    extern __shared__ unsigned smu[];

    const int tid  = threadIdx.x;
    const int lane = tid & 31;
    const int w    = tid >> 5;
    const int g    = lane >> 2;
    const int tig  = lane & 3;
    const int lane8 = lane & 7;
    const int lb3  = (lane >> 3) & 1;
    const int lb4  = (lane >> 4) & 1;

    const int qt = gridDim.x - 1 - blockIdx.x;
    const int h  = blockIdx.y;
    const int b  = blockIdx.z;

    const size_t rowQ0 = (size_t)b * Sn + qt * 64;
    const size_t qk_off = h * DH;
    const size_t v_row0 = (size_t)(b * NH + h) * DH;

    const unsigned smu_b = (unsigned)__cvta_generic_to_shared(smu);
    const int m0r = w * 16;
    const unsigned q_loff = (unsigned)((m0r + lane8 + lb3 * 8) * 144 + lb4 * 16);
    const unsigned n_loff = (unsigned)((lane8 + lb4 * 8) * 144 + lb3 * 16);

    #pragma unroll
    for (int it = 0; it < 4; it++) {
        int idx = tid + it * 128;
        int r = idx >> 3, q4 = idx & 7;
        const uint4* gh = (const uint4*)(g_Qh + (rowQ0 + r) * Dn + qk_off);
        const uint4* gl = (const uint4*)(g_Ql + (rowQ0 + r) * Dn + qk_off);
        ((uint4*)(smu + r * AP))[q4] = gh[q4];
        ((uint4*)(smu + ATILE + r * AP))[q4] = gl[q4];
    }

    float o[8][4];
    #pragma unroll
    for (int ni = 0; ni < 8; ni++)
        #pragma unroll
        for (int c = 0; c < 4; c++) o[ni][c] = 0.0f;
    float m0 = -INFINITY, m1 = -INFINITY, l0 = 0.0f, l1 = 0.0f;

    __syncthreads();

    for (int kt = 0; kt <= qt; kt++) {
        const size_t rowK0 = (size_t)b * Sn + kt * 64;
        #pragma unroll
        for (int it = 0; it < 4; it++) {
            int idx = tid + it * 128;
            int r = idx >> 3, q4 = idx & 7;
            const uint4* kh = (const uint4*)(g_Kh + (rowK0 + r) * Dn + qk_off);
            const uint4* kl = (const uint4*)(g_Kl + (rowK0 + r) * Dn + qk_off);
            ((uint4*)(smu + 2 * ATILE + r * AP))[q4] = kh[q4];
            ((uint4*)(smu + 3 * ATILE + r * AP))[q4] = kl[q4];
            const uint4* vh = (const uint4*)(g_Vth + (v_row0 + r) * Sn + kt * 64);
            const uint4* vl = (const uint4*)(g_Vtl + (v_row0 + r) * Sn + kt * 64);
            ((uint4*)(smu + 4 * ATILE + r * AP))[q4] = vh[q4];
            ((uint4*)(smu + 5 * ATILE + r * AP))[q4] = vl[q4];
        }
        __syncthreads();

        float s[8][4];
        #pragma unroll
        for (int ni = 0; ni < 8; ni++)
            #pragma unroll
            for (int c = 0; c < 4; c++) s[ni][c] = 0.0f;

        #pragma unroll
        for (int kk = 0; kk < 4; kk++) {
            unsigned ah[4], al[4];
            ldsm4(ah[0], ah[1], ah[2], ah[3], smu_b + q_loff + kk * 32);
            ldsm4(al[0], al[1], al[2], al[3], smu_b + ATB + q_loff + kk * 32);
            #pragma unroll
            for (int p = 0; p < 4; p++) {
                unsigned bh[4], bl[4];
                unsigned kd = smu_b + 2 * ATB + n_loff + (unsigned)(p * 16 * 144 + kk * 32);
                ldsm4(bh[0], bh[1], bh[2], bh[3], kd);
                ldsm4(bl[0], bl[1], bl[2], bl[3], kd + ATB);
                mma16816(s[2*p],   ah, bh);
                mma16816(s[2*p],   ah, bl);
                mma16816(s[2*p],   al, bh);
                mma16816(s[2*p+1], ah, bh + 2);
                mma16816(s[2*p+1], ah, bl + 2);
                mma16816(s[2*p+1], al, bh + 2);
            }
        }

        if (kt == qt) {
            #pragma unroll
            for (int ni = 0; ni < 8; ni++) {
                int col = ni * 8 + 2 * tig;
                int r0 = m0r + g, r1 = r0 + 8;
                if (col > r0)     s[ni][0] = -INFINITY;
                if (col + 1 > r0) s[ni][1] = -INFINITY;
                if (col > r1)     s[ni][2] = -INFINITY;
                if (col + 1 > r1) s[ni][3] = -INFINITY;
            }
        }

        float rm0 = -INFINITY, rm1 = -INFINITY;
        #pragma unroll
        for (int ni = 0; ni < 8; ni++) {
            rm0 = fmaxf(rm0, fmaxf(s[ni][0], s[ni][1]));
            rm1 = fmaxf(rm1, fmaxf(s[ni][2], s[ni][3]));
        }
        rm0 = fmaxf(rm0, __shfl_xor_sync(0xffffffffu, rm0, 1));
        rm0 = fmaxf(rm0, __shfl_xor_sync(0xffffffffu, rm0, 2));
        rm1 = fmaxf(rm1, __shfl_xor_sync(0xffffffffu, rm1, 1));
        rm1 = fmaxf(rm1, __shfl_xor_sync(0xffffffffu, rm1, 2));
        float mn0 = fmaxf(m0, rm0), mn1 = fmaxf(m1, rm1);

        float rs0 = 0.0f, rs1 = 0.0f;
        #pragma unroll
        for (int ni = 0; ni < 8; ni++) {
            s[ni][0] = __expf(s[ni][0] - mn0);
            s[ni][1] = __expf(s[ni][1] - mn0);
            s[ni][2] = __expf(s[ni][2] - mn1);
            s[ni][3] = __expf(s[ni][3] - mn1);
            rs0 += s[ni][0] + s[ni][1];
            rs1 += s[ni][2] + s[ni][3];
        }
        rs0 += __shfl_xor_sync(0xffffffffu, rs0, 1);
        rs0 += __shfl_xor_sync(0xffffffffu, rs0, 2);
        rs1 += __shfl_xor_sync(0xffffffffu, rs1, 1);
        rs1 += __shfl_xor_sync(0xffffffffu, rs1, 2);

        float al0 = __expf(m0 - mn0), al1 = __expf(m1 - mn1);
        l0 = l0 * al0 + rs0;
        l1 = l1 * al1 + rs1;
        m0 = mn0; m1 = mn1;
        #pragma unroll
        for (int ni = 0; ni < 8; ni++) {
            o[ni][0] *= al0; o[ni][1] *= al0;
            o[ni][2] *= al1; o[ni][3] *= al1;
        }

        #pragma unroll
        for (int kk = 0; kk < 4; kk++) {
            unsigned pah[4], pal[4];
            {
                __nv_bfloat16 h00,l00,h01,l01,h10,l10,h11,l11;
                split_bf16(s[2*kk][0], h00, l00);
                split_bf16(s[2*kk][1], h01, l01);
                split_bf16(s[2*kk][2], h10, l10);
                split_bf16(s[2*kk][3], h11, l11);
                pah[0] = pack2(h00, h01); pal[0] = pack2(l00, l01);
                pah[1] = pack2(h10, h11); pal[1] = pack2(l10, l11);
                split_bf16(s[2*kk+1][0], h00, l00);
                split_bf16(s[2*kk+1][1], h01, l01);
                split_bf16(s[2*kk+1][2], h10, l10);
                split_bf16(s[2*kk+1][3], h11, l11);
                pah[2] = pack2(h00, h01); pal[2] = pack2(l00, l01);
                pah[3] = pack2(h10, h11); pal[3] = pack2(l10, l11);
            }
            #pragma unroll
            for (int p = 0; p < 4; p++) {
                unsigned vh[4], vl[4];
                unsigned vd = smu_b + 4 * ATB + n_loff + (unsigned)(p * 16 * 144 + kk * 32);
                ldsm4(vh[0], vh[1], vh[2], vh[3], vd);
                ldsm4(vl[0], vl[1], vl[2], vl[3], vd + ATB);
                mma16816(o[2*p],   pah, vh);
                mma16816(o[2*p],   pah, vl);
                mma16816(o[2*p],   pal, vh);
                mma16816(o[2*p+1], pah, vh + 2);
                mma16816(o[2*p+1], pah, vl + 2);
                mma16816(o[2*p+1], pal, vh + 2);
            }
        }
        __syncthreads();
    }

    float inv0 = 1.0f / l0, inv1 = 1.0f / l1;
    size_t row0 = rowQ0 + w * 16 + g;
    size_t row1 = row0 + 8;
    #pragma unroll
    for (int ni = 0; ni < 8; ni++) {
        int col = h * DH + ni * 8 + 2 * tig;
        __half2 z0(__float2half_rn(o[ni][0] * inv0), __float2half_rn(o[ni][1] * inv0));
        __half2 z1(__float2half_rn(o[ni][2] * inv1), __float2half_rn(o[ni][3] * inv1));
        *(__half2*)&g_Ah[row0 * Dn + col] = z0;
        *(__half2*)&g_Ah[row1 * Dn + col] = z1;
    }
}

// ---------------------------------------------------------------------------
extern "C" void kernel_launch(void* const* d_in, const int* in_sizes, int n_in,
                              void* d_out, int out_size) {
    const float* x     = (const float*)d_in[0];
    const float* W_qkv = (const float*)d_in[2];
    const float* b_qkv = (const float*)d_in[3];
    const float* W_o   = (const float*)d_in[4];
    const float* b_o   = (const float*)d_in[5];
    const float* wq    = (const float*)d_in[6];
    const float* wk    = (const float*)d_in[7];
    float* out = (float*)d_out;

    void *ah, *wth, *wtl, *woth, *wotl;
    cudaGetSymbolAddress(&ah, g_Ah);
    cudaGetSymbolAddress(&wth, g_Wth);
    cudaGetSymbolAddress(&wtl, g_Wtl);
    cudaGetSymbolAddress(&woth, g_Woth);
    cudaGetSymbolAddress(&wotl, g_Wotl);

    cudaFuncSetAttribute(gemm_f16x2<1>,
                         cudaFuncAttributeMaxDynamicSharedMemorySize, GEMM_SMEM);
    cudaFuncSetAttribute(gemm_f16x2<0>,
                         cudaFuncAttributeMaxDynamicSharedMemorySize, GEMM_SMEM);
    cudaFuncSetAttribute(attn_mma_kernel,
                         cudaFuncAttributeMaxDynamicSharedMemorySize, ATTN_SMEM);

    // 0) Preprocessing: x -> fp16; transpose+split weights (fp16 hi/lo)
    cvt_f16_kernel<<<1024, 256>>>(x, (__half*)ah, (size_t)Mrows * Dn / 4);
    {
        dim3 grid(N3 / 32, Dn / 32);
        tsplit_f16_kernel<<<grid, dim3(32, 8)>>>(W_qkv, (__half*)wth,
                                                 (__half*)wtl, Dn, N3);
    }
    {
        dim3 grid(Dn / 32, Dn / 32);
        tsplit_f16_kernel<<<grid, dim3(32, 8)>>>(W_o, (__half*)woth,
                                                 (__half*)wotl, Dn, Dn);
    }

    // 1) QKV GEMM with fused rmsnorm/split + v-transpose/split epilogue
    {
        dim3 grid(N3 / 128, Mrows / 128);
        gemm_f16x2<1><<<grid, 256, GEMM_SMEM>>>(
            (const __half*)ah, (const __half*)wth, (const __half*)wtl,
            b_qkv, nullptr, wq, wk, N3, Dn);
    }

    // 2) Flash attention — writes fp16 z into g_Ah
    {
        dim3 grid(Sn / 64, NH, Bn);
        attn_mma_kernel<<<grid, 128, ATTN_SMEM>>>();
    }

    // 3) Output projection (plain epilogue)
    {
        dim3 grid(Dn / 128, Mrows / 128);
        gemm_f16x2<0><<<grid, 256, GEMM_SMEM>>>(
            (const __half*)ah, (const __half*)woth, (const __half*)wotl,
            b_o, out, nullptr, nullptr, Dn, Dn);
    }
}

// round 14
// speedup vs baseline: 1.0514x; 1.0303x over previous
#include <cuda_runtime.h>
#include <cuda_bf16.h>
#include <cuda_fp16.h>
#include <math.h>
#include <stdint.h>

#define Bn 4
#define Sn 2048
#define Dn 1024
#define NH 16
#define DH 64
#define Mrows (Bn*Sn)      // 8192
#define N3 (3*Dn)          // 3072

// Scratch (device globals: allocation-free per harness rules)
__device__ __half g_Ah[(size_t)Mrows * Dn];            // fp16(x) / fp16(attn out)
__device__ __half g_Wth[(size_t)N3 * Dn];              // W_qkv^T hi [N][K]
__device__ __half g_Wtl[(size_t)N3 * Dn];              // W_qkv^T lo
__device__ __half g_Woth[(size_t)Dn * Dn];             // W_o^T hi
__device__ __half g_Wotl[(size_t)Dn * Dn];
__device__ __half g_Qh[(size_t)Mrows * Dn];            // rmsnormed q split (fp16)
__device__ __half g_Ql[(size_t)Mrows * Dn];
__device__ __half g_Kh[(size_t)Mrows * Dn];
__device__ __half g_Kl[(size_t)Mrows * Dn];
__device__ __half g_Vth[(size_t)Mrows * Dn];           // V^T split: [(b*NH+h)*DH+d][s]
__device__ __half g_Vtl[(size_t)Mrows * Dn];

__device__ __forceinline__ void split_f16(float x, __half& h, __half& l) {
    h = __float2half_rn(x);
    l = __float2half_rn(x - __half2float(h));
}
__device__ __forceinline__ unsigned pack2h(__half lo, __half hi) {
    __half2 p(lo, hi);
    return *(unsigned*)&p;
}
__device__ __forceinline__ void mma16816h(float* c, const unsigned* a, const unsigned* b) {
    asm volatile(
        "mma.sync.aligned.m16n8k16.row.col.f32.f16.f16.f32 "
        "{%0,%1,%2,%3}, {%4,%5,%6,%7}, {%8,%9}, {%0,%1,%2,%3};"
        : "+f"(c[0]), "+f"(c[1]), "+f"(c[2]), "+f"(c[3])
        : "r"(a[0]), "r"(a[1]), "r"(a[2]), "r"(a[3]), "r"(b[0]), "r"(b[1]));
}
__device__ __forceinline__ void cp16(unsigned smem_addr, const void* gptr) {
    asm volatile("cp.async.cg.shared.global [%0], [%1], 16;"
                 :: "r"(smem_addr), "l"(gptr));
}
__device__ __forceinline__ void ldsm4(unsigned& r0, unsigned& r1,
                                      unsigned& r2, unsigned& r3, unsigned addr) {
    asm volatile("ldmatrix.sync.aligned.m8n8.x4.shared.b16 {%0,%1,%2,%3}, [%4];"
                 : "=r"(r0), "=r"(r1), "=r"(r2), "=r"(r3) : "r"(addr));
}

// ---------------------------------------------------------------------------
// fp32 -> fp16 convert (for x)
// ---------------------------------------------------------------------------
__global__ void cvt_f16_kernel(const float* __restrict__ in,
                               __half* __restrict__ out, size_t n4) {
    size_t i = (size_t)blockIdx.x * blockDim.x + threadIdx.x;
    size_t stride = (size_t)gridDim.x * blockDim.x;
    for (; i < n4; i += stride) {
        float4 v = ((const float4*)in)[i];
        __half2 a(__float2half_rn(v.x), __float2half_rn(v.y));
        __half2 b(__float2half_rn(v.z), __float2half_rn(v.w));
        ((__half2*)out)[i * 2]     = a;
        ((__half2*)out)[i * 2 + 1] = b;
    }
}

// ---------------------------------------------------------------------------
// Transpose + fp16 hi/lo split: W[K][N] fp32 -> Wt hi/lo [N][K] fp16
// ---------------------------------------------------------------------------
__global__ void tsplit_f16_kernel(const float* __restrict__ W,
                                  __half* __restrict__ th,
                                  __half* __restrict__ tl, int K, int N) {
    __shared__ float t[32][33];
    int n0 = blockIdx.x * 32, k0 = blockIdx.y * 32;
    int tx = threadIdx.x, ty = threadIdx.y;           // (32, 8)
    #pragma unroll
    for (int i = ty; i < 32; i += 8)
        t[i][tx] = W[(size_t)(k0 + i) * N + n0 + tx];
    __syncthreads();
    #pragma unroll
    for (int i = ty; i < 32; i += 8) {
        float v = t[tx][i];
        __half h, l;
        split_f16(v, h, l);
        th[(size_t)(n0 + i) * K + k0 + tx] = h;
        tl[(size_t)(n0 + i) * K + k0 + tx] = l;
    }
}

// ---------------------------------------------------------------------------
// fp16x2 triple-buffered cp.async GEMM (round-9 verified mainloop).
// FUSED=1 (QKV): epilogue does rmsnorm+fp16-split for q/k sections and
// transpose+fp16-split for the v section (no fp32 C written at all).
// FUSED=0 (O-proj): plain bias + fp32 store to C.
// ---------------------------------------------------------------------------
#define BKK 32
#define PITCH 20                       // 16 data u32 + 4 pad (5x16B, coprime 8)
#define TILE_U32 (128 * PITCH)
#define TILEB (TILE_U32 * 4)
#define STAGE_U32 (3 * TILE_U32)       // A, Bh, Bl
#define GEMM_SMEM (3 * STAGE_U32 * 4)  // 3 stages = 92160 B (>= 128*129*4 transpose)

template<int FUSED>
__global__ __launch_bounds__(256, 2)
void gemm_f16x2(const __half* __restrict__ A,
                const __half* __restrict__ Bth,
                const __half* __restrict__ Btl,
                const float* __restrict__ bias,
                float* __restrict__ C,
                const float* __restrict__ wq,
                const float* __restrict__ wk,
                int Nz, int Kz) {
    extern __shared__ unsigned sm[];

    const int tid  = threadIdx.x;
    const int lane = tid & 31;
    const int wid  = tid >> 5;
    const int wm   = wid >> 2;
    const int wn   = wid & 3;
    const int g    = lane >> 2;
    const int tig  = lane & 3;
    const int lane8 = lane & 7;
    const int lb3  = (lane >> 3) & 1;
    const int lb4  = (lane >> 4) & 1;

    const int rowBase = blockIdx.y * 128;
    const int colBase = blockIdx.x * 128;

    const int r0 = tid >> 2;           // cp.async row, +64 for it2=1
    const int c4 = tid & 3;            // 16B sector in row

    const unsigned smem_base = (unsigned)__cvta_generic_to_shared(sm);

    const unsigned a_off = (unsigned)((wm * 64 + lane8 + lb3 * 8) * 80 + lb4 * 16);
    const unsigned b_off = (unsigned)((wn * 32 + lane8 + lb4 * 8) * 80 + lb3 * 16);

    float acc[4][4][4];
    #pragma unroll
    for (int i = 0; i < 4; i++)
        #pragma unroll
        for (int j = 0; j < 4; j++)
            #pragma unroll
            for (int q = 0; q < 4; q++) acc[i][j][q] = 0.0f;

    const int NIT = Kz / BKK;

    auto load_stage = [&](int it, int buf) {
        const int k0 = it * BKK;
        const unsigned sbase = smem_base + buf * STAGE_U32 * 4;
        #pragma unroll
        for (int it2 = 0; it2 < 2; it2++) {
            int row = r0 + it2 * 64;
            unsigned soff = (unsigned)(row * PITCH + c4 * 4) * 4;
            const __half* gA  = A   + (size_t)(rowBase + row) * Kz + k0 + c4 * 8;
            const __half* gBh = Bth + (size_t)(colBase + row) * Kz + k0 + c4 * 8;
            const __half* gBl = Btl + (size_t)(colBase + row) * Kz + k0 + c4 * 8;
            cp16(sbase + soff, gA);
            cp16(sbase + TILEB + soff, gBh);
            cp16(sbase + 2 * TILEB + soff, gBl);
        }
        asm volatile("cp.async.commit_group;");
    };

    load_stage(0, 0);
    load_stage(1, 1);

    for (int it = 0; it < NIT; it++) {
        const int buf = it % 3;
        if (it + 2 < NIT) {
            load_stage(it + 2, (it + 2) % 3);
            asm volatile("cp.async.wait_group 2;");
        } else if (it + 1 < NIT) {
            asm volatile("cp.async.wait_group 1;");
        } else {
            asm volatile("cp.async.wait_group 0;");
        }
        __syncthreads();

        const unsigned stg = smem_base + buf * STAGE_U32 * 4;

        #pragma unroll
        for (int kk8 = 0; kk8 < 2; kk8++) {
            unsigned a[4][4], bhi[4][2], blo[4][2];
            #pragma unroll
            for (int mi = 0; mi < 4; mi++) {
                unsigned ad = stg + a_off + (unsigned)(mi * 16 * 80 + kk8 * 32);
                ldsm4(a[mi][0], a[mi][1], a[mi][2], a[mi][3], ad);
            }
            #pragma unroll
            for (int p = 0; p < 2; p++) {
                unsigned bd = stg + TILEB + b_off + (unsigned)(p * 16 * 80 + kk8 * 32);
                ldsm4(bhi[2*p][0], bhi[2*p][1], bhi[2*p+1][0], bhi[2*p+1][1], bd);
                ldsm4(blo[2*p][0], blo[2*p][1], blo[2*p+1][0], blo[2*p+1][1], bd + TILEB);
            }
            #pragma unroll
            for (int mi = 0; mi < 4; mi++)
                #pragma unroll
                for (int ni = 0; ni < 4; ni++) {
                    mma16816h(acc[mi][ni], a[mi], bhi[ni]);
                    mma16816h(acc[mi][ni], a[mi], blo[ni]);
                }
        }
        __syncthreads();
    }
    // NOTE: final __syncthreads() above means all smem stage reads are done;
    // the epilogue may reuse sm[].

    if (!FUSED) {
        // Plain epilogue: bias + fp32 store
        #pragma unroll
        for (int mi = 0; mi < 4; mi++) {
            int row0 = rowBase + wm * 64 + mi * 16 + g;
            int row1 = row0 + 8;
            #pragma unroll
            for (int ni = 0; ni < 4; ni++) {
                int col = colBase + wn * 32 + ni * 8 + tig * 2;
                float b0 = __ldg(&bias[col]);
                float b1 = __ldg(&bias[col + 1]);
                C[(size_t)row0 * Nz + col]     = acc[mi][ni][0] + b0;
                C[(size_t)row0 * Nz + col + 1] = acc[mi][ni][1] + b1;
                C[(size_t)row1 * Nz + col]     = acc[mi][ni][2] + b0;
                C[(size_t)row1 * Nz + col + 1] = acc[mi][ni][3] + b1;
            }
        }
        return;
    }

    // ----- FUSED epilogue (QKV) -----
    #pragma unroll
    for (int ni = 0; ni < 4; ni++) {
        int col = colBase + wn * 32 + ni * 8 + tig * 2;
        float b0 = __ldg(&bias[col]);
        float b1 = __ldg(&bias[col + 1]);
        #pragma unroll
        for (int mi = 0; mi < 4; mi++) {
            acc[mi][ni][0] += b0; acc[mi][ni][1] += b1;
            acc[mi][ni][2] += b0; acc[mi][ni][3] += b1;
        }
    }

    const int sec = colBase >> 10;         // 0=q, 1=k, 2=v
    const int cb  = colBase & 1023;
    const int bb  = rowBase >> 11;         // batch (Sn = 2048)
    const int s0row = rowBase & 2047;

    if (sec < 2) {
        // --- RMSNorm + fp16 split for q/k ---
        float* red = (float*)sm;           // [4 warpsN][128 rows]
        #pragma unroll
        for (int mi = 0; mi < 4; mi++) {
            float l0 = 0.0f, l1 = 0.0f;
            #pragma unroll
            for (int ni = 0; ni < 4; ni++) {
                l0 += acc[mi][ni][0] * acc[mi][ni][0] + acc[mi][ni][1] * acc[mi][ni][1];
                l1 += acc[mi][ni][2] * acc[mi][ni][2] + acc[mi][ni][3] * acc[mi][ni][3];
            }
            l0 += __shfl_xor_sync(0xffffffffu, l0, 1);
            l0 += __shfl_xor_sync(0xffffffffu, l0, 2);
            l1 += __shfl_xor_sync(0xffffffffu, l1, 1);
            l1 += __shfl_xor_sync(0xffffffffu, l1, 2);
            if (tig == 0) {
                int lr = wm * 64 + mi * 16 + g;
                red[wn * 128 + lr]     = l0;
                red[wn * 128 + lr + 8] = l1;
            }
        }
        __syncthreads();

        const float* wv = sec ? wk : wq;
        __half* dh = sec ? g_Kh : g_Qh;
        __half* dl = sec ? g_Kl : g_Ql;
        const int head = (cb >> 6) + (wn >> 1);

        #pragma unroll
        for (int mi = 0; mi < 4; mi++) {
            int lr = wm * 64 + mi * 16 + g;
            float ssq0 = red[wn * 128 + lr]     + red[(wn ^ 1) * 128 + lr];
            float ssq1 = red[wn * 128 + lr + 8] + red[(wn ^ 1) * 128 + lr + 8];
            float inv0 = rsqrtf(ssq0 * (1.0f / DH) + 1e-6f);
            float inv1 = rsqrtf(ssq1 * (1.0f / DH) + 1e-6f);
            size_t row0 = (size_t)(rowBase + lr);
            size_t row1 = row0 + 8;
            #pragma unroll
            for (int ni = 0; ni < 4; ni++) {
                int ic = (wn & 1) * 32 + ni * 8 + tig * 2;
                float wf0 = __ldg(&wv[ic]);
                float wf1 = __ldg(&wv[ic + 1]);
                size_t o0 = row0 * Dn + head * 64 + ic;
                size_t o1 = row1 * Dn + head * 64 + ic;
                __half h0, lo0, h1, lo1;
                split_f16(acc[mi][ni][0] * inv0 * wf0, h0, lo0);
                split_f16(acc[mi][ni][1] * inv0 * wf1, h1, lo1);
                *(unsigned*)&dh[o0] = pack2h(h0, h1);
                *(unsigned*)&dl[o0] = pack2h(lo0, lo1);
                split_f16(acc[mi][ni][2] * inv1 * wf0, h0, lo0);
                split_f16(acc[mi][ni][3] * inv1 * wf1, h1, lo1);
                *(unsigned*)&dh[o1] = pack2h(h0, h1);
                *(unsigned*)&dl[o1] = pack2h(lo0, lo1);
            }
        }
    } else {
        // --- V: transpose via smem, fp16 split, write [d][s] ---
        float (*vt)[129] = (float(*)[129])sm;   // 128 x 129 fp32 = 66048 B
        #pragma unroll
        for (int mi = 0; mi < 4; mi++) {
            int lr0 = wm * 64 + mi * 16 + g;
            #pragma unroll
            for (int ni = 0; ni < 4; ni++) {
                int lc = wn * 32 + ni * 8 + tig * 2;
                vt[lr0][lc]     = acc[mi][ni][0];
                vt[lr0][lc + 1] = acc[mi][ni][1];
                vt[lr0 + 8][lc]     = acc[mi][ni][2];
                vt[lr0 + 8][lc + 1] = acc[mi][ni][3];
            }
        }
        __syncthreads();

        int d  = tid >> 1;               // 0..127
        int sh = (tid & 1) * 64;         // s half
        int hg = (cb >> 6) + (d >> 6);   // global head
        int dl_ = d & 63;
        size_t base = ((size_t)(bb * NH + hg) * DH + dl_) * Sn + s0row + sh;
        #pragma unroll
        for (int i = 0; i < 64; i += 2) {
            float v0 = vt[sh + i][d];
            float v1 = vt[sh + i + 1][d];
            __half h0, l0, h1, l1;
            split_f16(v0, h0, l0);
            split_f16(v1, h1, l1);
            *(unsigned*)&g_Vth[base + i] = pack2h(h0, h1);
            *(unsigned*)&g_Vtl[base + i] = pack2h(l0, l1);
        }
    }
}

// ---------------------------------------------------------------------------
// Flash attention, fp16 mma.sync + ldmatrix, 64-row q tiles.
// QK^T: fp16x3 (q,k hi/lo — 22-bit effective). PV: fp16 P (single) x
// fp16 hi/lo V — 2 MMAs instead of 3. Epilogue writes fp16 z into g_Ah.
// ---------------------------------------------------------------------------
#define AP 36
#define ATILE (64 * AP)
#define ATB (ATILE * 4)                // tile bytes 9216
#define ATTN_SMEM (6 * ATILE * 4)      // 55296 B

__global__ __launch_bounds__(128) void attn_mma_kernel() {
    extern __shared__ unsigned smu[];

    const int tid  = threadIdx.x;
    const int lane = tid & 31;
    const int w    = tid >> 5;
    const int g    = lane >> 2;
    const int tig  = lane & 3;
    const int lane8 = lane & 7;
    const int lb3  = (lane >> 3) & 1;
    const int lb4  = (lane >> 4) & 1;

    const int qt = gridDim.x - 1 - blockIdx.x;
    const int h  = blockIdx.y;
    const int b  = blockIdx.z;

    const size_t rowQ0 = (size_t)b * Sn + qt * 64;
    const size_t qk_off = h * DH;
    const size_t v_row0 = (size_t)(b * NH + h) * DH;

    const unsigned smu_b = (unsigned)__cvta_generic_to_shared(smu);
    const int m0r = w * 16;
    const unsigned q_loff = (unsigned)((m0r + lane8 + lb3 * 8) * 144 + lb4 * 16);
    const unsigned n_loff = (unsigned)((lane8 + lb4 * 8) * 144 + lb3 * 16);

    #pragma unroll
    for (int it = 0; it < 4; it++) {
        int idx = tid + it * 128;
        int r = idx >> 3, q4 = idx & 7;
        const uint4* gh = (const uint4*)(g_Qh + (rowQ0 + r) * Dn + qk_off);
        const uint4* gl = (const uint4*)(g_Ql + (rowQ0 + r) * Dn + qk_off);
        ((uint4*)(smu + r * AP))[q4] = gh[q4];
        ((uint4*)(smu + ATILE + r * AP))[q4] = gl[q4];
    }

    float o[8][4];
    #pragma unroll
    for (int ni = 0; ni < 8; ni++)
        #pragma unroll
        for (int c = 0; c < 4; c++) o[ni][c] = 0.0f;
    float m0 = -INFINITY, m1 = -INFINITY, l0 = 0.0f, l1 = 0.0f;

    __syncthreads();

    for (int kt = 0; kt <= qt; kt++) {
        const size_t rowK0 = (size_t)b * Sn + kt * 64;
        #pragma unroll
        for (int it = 0; it < 4; it++) {
            int idx = tid + it * 128;
            int r = idx >> 3, q4 = idx & 7;
            const uint4* kh = (const uint4*)(g_Kh + (rowK0 + r) * Dn + qk_off);
            const uint4* kl = (const uint4*)(g_Kl + (rowK0 + r) * Dn + qk_off);
            ((uint4*)(smu + 2 * ATILE + r * AP))[q4] = kh[q4];
            ((uint4*)(smu + 3 * ATILE + r * AP))[q4] = kl[q4];
            const uint4* vh = (const uint4*)(g_Vth + (v_row0 + r) * Sn + kt * 64);
            const uint4* vl = (const uint4*)(g_Vtl + (v_row0 + r) * Sn + kt * 64);
            ((uint4*)(smu + 4 * ATILE + r * AP))[q4] = vh[q4];
            ((uint4*)(smu + 5 * ATILE + r * AP))[q4] = vl[q4];
        }
        __syncthreads();

        float s[8][4];
        #pragma unroll
        for (int ni = 0; ni < 8; ni++)
            #pragma unroll
            for (int c = 0; c < 4; c++) s[ni][c] = 0.0f;

        #pragma unroll
        for (int kk = 0; kk < 4; kk++) {
            unsigned ah[4], al[4];
            ldsm4(ah[0], ah[1], ah[2], ah[3], smu_b + q_loff + kk * 32);
            ldsm4(al[0], al[1], al[2], al[3], smu_b + ATB + q_loff + kk * 32);
            #pragma unroll
            for (int p = 0; p < 4; p++) {
                unsigned bh[4], bl[4];
                unsigned kd = smu_b + 2 * ATB + n_loff + (unsigned)(p * 16 * 144 + kk * 32);
                ldsm4(bh[0], bh[1], bh[2], bh[3], kd);
                ldsm4(bl[0], bl[1], bl[2], bl[3], kd + ATB);
                mma16816h(s[2*p],   ah, bh);
                mma16816h(s[2*p],   ah, bl);
                mma16816h(s[2*p],   al, bh);
                mma16816h(s[2*p+1], ah, bh + 2);
                mma16816h(s[2*p+1], ah, bl + 2);
                mma16816h(s[2*p+1], al, bh + 2);
            }
        }

        if (kt == qt) {
            #pragma unroll
            for (int ni = 0; ni < 8; ni++) {
                int col = ni * 8 + 2 * tig;
                int r0 = m0r + g, r1 = r0 + 8;
                if (col > r0)     s[ni][0] = -INFINITY;
                if (col + 1 > r0) s[ni][1] = -INFINITY;
                if (col > r1)     s[ni][2] = -INFINITY;
                if (col + 1 > r1) s[ni][3] = -INFINITY;
            }
        }

        float rm0 = -INFINITY, rm1 = -INFINITY;
        #pragma unroll
        for (int ni = 0; ni < 8; ni++) {
            rm0 = fmaxf(rm0, fmaxf(s[ni][0], s[ni][1]));
            rm1 = fmaxf(rm1, fmaxf(s[ni][2], s[ni][3]));
        }
        rm0 = fmaxf(rm0, __shfl_xor_sync(0xffffffffu, rm0, 1));
        rm0 = fmaxf(rm0, __shfl_xor_sync(0xffffffffu, rm0, 2));
        rm1 = fmaxf(rm1, __shfl_xor_sync(0xffffffffu, rm1, 1));
        rm1 = fmaxf(rm1, __shfl_xor_sync(0xffffffffu, rm1, 2));
        float mn0 = fmaxf(m0, rm0), mn1 = fmaxf(m1, rm1);

        float rs0 = 0.0f, rs1 = 0.0f;
        #pragma unroll
        for (int ni = 0; ni < 8; ni++) {
            s[ni][0] = __expf(s[ni][0] - mn0);
            s[ni][1] = __expf(s[ni][1] - mn0);
            s[ni][2] = __expf(s[ni][2] - mn1);
            s[ni][3] = __expf(s[ni][3] - mn1);
            rs0 += s[ni][0] + s[ni][1];
            rs1 += s[ni][2] + s[ni][3];
        }
        rs0 += __shfl_xor_sync(0xffffffffu, rs0, 1);
        rs0 += __shfl_xor_sync(0xffffffffu, rs0, 2);
        rs1 += __shfl_xor_sync(0xffffffffu, rs1, 1);
        rs1 += __shfl_xor_sync(0xffffffffu, rs1, 2);

        float al0 = __expf(m0 - mn0), al1 = __expf(m1 - mn1);
        l0 = l0 * al0 + rs0;
        l1 = l1 * al1 + rs1;
        m0 = mn0; m1 = mn1;
        #pragma unroll
        for (int ni = 0; ni < 8; ni++) {
            o[ni][0] *= al0; o[ni][1] *= al0;
            o[ni][2] *= al1; o[ni][3] *= al1;
        }

        // ---- O += P @ V : P as single fp16, V fp16 hi/lo (2 MMAs) ----
        #pragma unroll
        for (int kk = 0; kk < 4; kk++) {
            unsigned pah[4];
            {
                __half2 p0(__float2half_rn(s[2*kk][0]),   __float2half_rn(s[2*kk][1]));
                __half2 p1(__float2half_rn(s[2*kk][2]),   __float2half_rn(s[2*kk][3]));
                __half2 p2(__float2half_rn(s[2*kk+1][0]), __float2half_rn(s[2*kk+1][1]));
                __half2 p3(__float2half_rn(s[2*kk+1][2]), __float2half_rn(s[2*kk+1][3]));
                pah[0] = *(unsigned*)&p0;
                pah[1] = *(unsigned*)&p1;
                pah[2] = *(unsigned*)&p2;
                pah[3] = *(unsigned*)&p3;
            }
            #pragma unroll
            for (int p = 0; p < 4; p++) {
                unsigned vh[4], vl[4];
                unsigned vd = smu_b + 4 * ATB + n_loff + (unsigned)(p * 16 * 144 + kk * 32);
                ldsm4(vh[0], vh[1], vh[2], vh[3], vd);
                ldsm4(vl[0], vl[1], vl[2], vl[3], vd + ATB);
                mma16816h(o[2*p],   pah, vh);
                mma16816h(o[2*p],   pah, vl);
                mma16816h(o[2*p+1], pah, vh + 2);
                mma16816h(o[2*p+1], pah, vl + 2);
            }
        }
        __syncthreads();
    }

    float inv0 = 1.0f / l0, inv1 = 1.0f / l1;
    size_t row0 = rowQ0 + w * 16 + g;
    size_t row1 = row0 + 8;
    #pragma unroll
    for (int ni = 0; ni < 8; ni++) {
        int col = h * DH + ni * 8 + 2 * tig;
        __half2 z0(__float2half_rn(o[ni][0] * inv0), __float2half_rn(o[ni][1] * inv0));
        __half2 z1(__float2half_rn(o[ni][2] * inv1), __float2half_rn(o[ni][3] * inv1));
        *(__half2*)&g_Ah[row0 * Dn + col] = z0;
        *(__half2*)&g_Ah[row1 * Dn + col] = z1;
    }
}

// ---------------------------------------------------------------------------
extern "C" void kernel_launch(void* const* d_in, const int* in_sizes, int n_in,
                              void* d_out, int out_size) {
    const float* x     = (const float*)d_in[0];
    const float* W_qkv = (const float*)d_in[2];
    const float* b_qkv = (const float*)d_in[3];
    const float* W_o   = (const float*)d_in[4];
    const float* b_o   = (const float*)d_in[5];
    const float* wq    = (const float*)d_in[6];
    const float* wk    = (const float*)d_in[7];
    float* out = (float*)d_out;

    void *ah, *wth, *wtl, *woth, *wotl;
    cudaGetSymbolAddress(&ah, g_Ah);
    cudaGetSymbolAddress(&wth, g_Wth);
    cudaGetSymbolAddress(&wtl, g_Wtl);
    cudaGetSymbolAddress(&woth, g_Woth);
    cudaGetSymbolAddress(&wotl, g_Wotl);

    cudaFuncSetAttribute(gemm_f16x2<1>,
                         cudaFuncAttributeMaxDynamicSharedMemorySize, GEMM_SMEM);
    cudaFuncSetAttribute(gemm_f16x2<0>,
                         cudaFuncAttributeMaxDynamicSharedMemorySize, GEMM_SMEM);
    cudaFuncSetAttribute(attn_mma_kernel,
                         cudaFuncAttributeMaxDynamicSharedMemorySize, ATTN_SMEM);

    // 0) Preprocessing: x -> fp16; transpose+split weights (fp16 hi/lo)
    cvt_f16_kernel<<<1024, 256>>>(x, (__half*)ah, (size_t)Mrows * Dn / 4);
    {
        dim3 grid(N3 / 32, Dn / 32);
        tsplit_f16_kernel<<<grid, dim3(32, 8)>>>(W_qkv, (__half*)wth,
                                                 (__half*)wtl, Dn, N3);
    }
    {
        dim3 grid(Dn / 32, Dn / 32);
        tsplit_f16_kernel<<<grid, dim3(32, 8)>>>(W_o, (__half*)woth,
                                                 (__half*)wotl, Dn, Dn);
    }

    // 1) QKV GEMM with fused rmsnorm/split + v-transpose/split epilogue
    {
        dim3 grid(N3 / 128, Mrows / 128);
        gemm_f16x2<1><<<grid, 256, GEMM_SMEM>>>(
            (const __half*)ah, (const __half*)wth, (const __half*)wtl,
            b_qkv, nullptr, wq, wk, N3, Dn);
    }

    // 2) Flash attention — writes fp16 z into g_Ah
    {
        dim3 grid(Sn / 64, NH, Bn);
        attn_mma_kernel<<<grid, 128, ATTN_SMEM>>>();
    }

    // 3) Output projection (plain epilogue)
    {
        dim3 grid(Dn / 128, Mrows / 128);
        gemm_f16x2<0><<<grid, 256, GEMM_SMEM>>>(
            (const __half*)ah, (const __half*)woth, (const __half*)wotl,
            b_o, out, nullptr, nullptr, Dn, Dn);
    }
}

// round 15
// speedup vs baseline: 1.1487x; 1.0926x over previous
#include <cuda_runtime.h>
#include <cuda_bf16.h>
#include <cuda_fp16.h>
#include <math.h>
#include <stdint.h>

#define Bn 4
#define Sn 2048
#define Dn 1024
#define NH 16
#define DH 64
#define Mrows (Bn*Sn)      // 8192
#define N3 (3*Dn)          // 3072

// Scratch (device globals: allocation-free per harness rules)
__device__ __half g_Ah[(size_t)Mrows * Dn];            // fp16(x) / fp16(attn out)
__device__ __half g_Wth[(size_t)N3 * Dn];              // W_qkv^T hi [N][K]
__device__ __half g_Wtl[(size_t)N3 * Dn];              // W_qkv^T lo
__device__ __half g_Woth[(size_t)Dn * Dn];             // W_o^T (fp16 single)
__device__ __half g_Qh[(size_t)Mrows * Dn];            // rmsnormed q split (fp16)
__device__ __half g_Ql[(size_t)Mrows * Dn];
__device__ __half g_Kh[(size_t)Mrows * Dn];
__device__ __half g_Kl[(size_t)Mrows * Dn];
__device__ __half g_Vth[(size_t)Mrows * Dn];           // V^T split: [(b*NH+h)*DH+d][s]
__device__ __half g_Vtl[(size_t)Mrows * Dn];

__device__ __forceinline__ void split_f16(float x, __half& h, __half& l) {
    h = __float2half_rn(x);
    l = __float2half_rn(x - __half2float(h));
}
__device__ __forceinline__ unsigned pack2h(__half lo, __half hi) {
    __half2 p(lo, hi);
    return *(unsigned*)&p;
}
__device__ __forceinline__ void mma16816h(float* c, const unsigned* a, const unsigned* b) {
    asm volatile(
        "mma.sync.aligned.m16n8k16.row.col.f32.f16.f16.f32 "
        "{%0,%1,%2,%3}, {%4,%5,%6,%7}, {%8,%9}, {%0,%1,%2,%3};"
        : "+f"(c[0]), "+f"(c[1]), "+f"(c[2]), "+f"(c[3])
        : "r"(a[0]), "r"(a[1]), "r"(a[2]), "r"(a[3]), "r"(b[0]), "r"(b[1]));
}
__device__ __forceinline__ void cp16(unsigned smem_addr, const void* gptr) {
    asm volatile("cp.async.cg.shared.global [%0], [%1], 16;"
                 :: "r"(smem_addr), "l"(gptr));
}
__device__ __forceinline__ void ldsm4(unsigned& r0, unsigned& r1,
                                      unsigned& r2, unsigned& r3, unsigned addr) {
    asm volatile("ldmatrix.sync.aligned.m8n8.x4.shared.b16 {%0,%1,%2,%3}, [%4];"
                 : "=r"(r0), "=r"(r1), "=r"(r2), "=r"(r3) : "r"(addr));
}

// ---------------------------------------------------------------------------
// fp32 -> fp16 convert (for x)
// ---------------------------------------------------------------------------
__global__ void cvt_f16_kernel(const float* __restrict__ in,
                               __half* __restrict__ out, size_t n4) {
    size_t i = (size_t)blockIdx.x * blockDim.x + threadIdx.x;
    size_t stride = (size_t)gridDim.x * blockDim.x;
    for (; i < n4; i += stride) {
        float4 v = ((const float4*)in)[i];
        __half2 a(__float2half_rn(v.x), __float2half_rn(v.y));
        __half2 b(__float2half_rn(v.z), __float2half_rn(v.w));
        ((__half2*)out)[i * 2]     = a;
        ((__half2*)out)[i * 2 + 1] = b;
    }
}

// ---------------------------------------------------------------------------
// Transpose + fp16 split: W[K][N] fp32 -> Wt hi (and optionally lo) [N][K]
// ---------------------------------------------------------------------------
__global__ void tsplit_f16_kernel(const float* __restrict__ W,
                                  __half* __restrict__ th,
                                  __half* __restrict__ tl, int K, int N) {
    __shared__ float t[32][33];
    int n0 = blockIdx.x * 32, k0 = blockIdx.y * 32;
    int tx = threadIdx.x, ty = threadIdx.y;           // (32, 8)
    #pragma unroll
    for (int i = ty; i < 32; i += 8)
        t[i][tx] = W[(size_t)(k0 + i) * N + n0 + tx];
    __syncthreads();
    #pragma unroll
    for (int i = ty; i < 32; i += 8) {
        float v = t[tx][i];
        __half h, l;
        split_f16(v, h, l);
        th[(size_t)(n0 + i) * K + k0 + tx] = h;
        if (tl) tl[(size_t)(n0 + i) * K + k0 + tx] = l;
    }
}

// ---------------------------------------------------------------------------
// fp16 triple-buffered cp.async GEMM.
// W-side correction (Bl term) is applied only where softmax amplifies noise:
//   FUSED=1 (QKV): Bl used for q/k column tiles (colBase < 2048), skipped
//                  for the v section. Fused rmsnorm/v-transpose epilogue.
//   FUSED=0 (O-proj): single-term (no Bl), plain bias + fp32 store.
// ---------------------------------------------------------------------------
#define BKK 32
#define PITCH 20                       // 16 data u32 + 4 pad (5x16B, coprime 8)
#define TILE_U32 (128 * PITCH)
#define TILEB (TILE_U32 * 4)
#define STAGE_U32 (3 * TILE_U32)       // A, Bh, Bl
#define GEMM_SMEM (3 * STAGE_U32 * 4)  // 3 stages = 92160 B (>= 128*129*4 transpose)

template<int FUSED>
__global__ __launch_bounds__(256, 2)
void gemm_f16x2(const __half* __restrict__ A,
                const __half* __restrict__ Bth,
                const __half* __restrict__ Btl,
                const float* __restrict__ bias,
                float* __restrict__ C,
                const float* __restrict__ wq,
                const float* __restrict__ wk,
                int Nz, int Kz) {
    extern __shared__ unsigned sm[];

    const int tid  = threadIdx.x;
    const int lane = tid & 31;
    const int wid  = tid >> 5;
    const int wm   = wid >> 2;
    const int wn   = wid & 3;
    const int g    = lane >> 2;
    const int tig  = lane & 3;
    const int lane8 = lane & 7;
    const int lb3  = (lane >> 3) & 1;
    const int lb4  = (lane >> 4) & 1;

    const int rowBase = blockIdx.y * 128;
    const int colBase = blockIdx.x * 128;
    const bool use_lo = FUSED ? (colBase < 2048) : false;

    const int r0 = tid >> 2;           // cp.async row, +64 for it2=1
    const int c4 = tid & 3;            // 16B sector in row

    const unsigned smem_base = (unsigned)__cvta_generic_to_shared(sm);

    const unsigned a_off = (unsigned)((wm * 64 + lane8 + lb3 * 8) * 80 + lb4 * 16);
    const unsigned b_off = (unsigned)((wn * 32 + lane8 + lb4 * 8) * 80 + lb3 * 16);

    float acc[4][4][4];
    #pragma unroll
    for (int i = 0; i < 4; i++)
        #pragma unroll
        for (int j = 0; j < 4; j++)
            #pragma unroll
            for (int q = 0; q < 4; q++) acc[i][j][q] = 0.0f;

    const int NIT = Kz / BKK;

    auto load_stage = [&](int it, int buf) {
        const int k0 = it * BKK;
        const unsigned sbase = smem_base + buf * STAGE_U32 * 4;
        #pragma unroll
        for (int it2 = 0; it2 < 2; it2++) {
            int row = r0 + it2 * 64;
            unsigned soff = (unsigned)(row * PITCH + c4 * 4) * 4;
            const __half* gA  = A   + (size_t)(rowBase + row) * Kz + k0 + c4 * 8;
            const __half* gBh = Bth + (size_t)(colBase + row) * Kz + k0 + c4 * 8;
            cp16(sbase + soff, gA);
            cp16(sbase + TILEB + soff, gBh);
            if (use_lo) {
                const __half* gBl = Btl + (size_t)(colBase + row) * Kz + k0 + c4 * 8;
                cp16(sbase + 2 * TILEB + soff, gBl);
            }
        }
        asm volatile("cp.async.commit_group;");
    };

    load_stage(0, 0);
    load_stage(1, 1);

    for (int it = 0; it < NIT; it++) {
        const int buf = it % 3;
        if (it + 2 < NIT) {
            load_stage(it + 2, (it + 2) % 3);
            asm volatile("cp.async.wait_group 2;");
        } else if (it + 1 < NIT) {
            asm volatile("cp.async.wait_group 1;");
        } else {
            asm volatile("cp.async.wait_group 0;");
        }
        __syncthreads();

        const unsigned stg = smem_base + buf * STAGE_U32 * 4;

        #pragma unroll
        for (int kk8 = 0; kk8 < 2; kk8++) {
            unsigned a[4][4], bhi[4][2], blo[4][2];
            #pragma unroll
            for (int mi = 0; mi < 4; mi++) {
                unsigned ad = stg + a_off + (unsigned)(mi * 16 * 80 + kk8 * 32);
                ldsm4(a[mi][0], a[mi][1], a[mi][2], a[mi][3], ad);
            }
            #pragma unroll
            for (int p = 0; p < 2; p++) {
                unsigned bd = stg + TILEB + b_off + (unsigned)(p * 16 * 80 + kk8 * 32);
                ldsm4(bhi[2*p][0], bhi[2*p][1], bhi[2*p+1][0], bhi[2*p+1][1], bd);
            }
            if (use_lo) {
                #pragma unroll
                for (int p = 0; p < 2; p++) {
                    unsigned bd = stg + 2 * TILEB + b_off + (unsigned)(p * 16 * 80 + kk8 * 32);
                    ldsm4(blo[2*p][0], blo[2*p][1], blo[2*p+1][0], blo[2*p+1][1], bd);
                }
            }
            #pragma unroll
            for (int mi = 0; mi < 4; mi++)
                #pragma unroll
                for (int ni = 0; ni < 4; ni++) {
                    mma16816h(acc[mi][ni], a[mi], bhi[ni]);
                    if (use_lo) mma16816h(acc[mi][ni], a[mi], blo[ni]);
                }
        }
        __syncthreads();
    }
    // NOTE: final __syncthreads() above means all smem stage reads are done;
    // the epilogue may reuse sm[].

    if (!FUSED) {
        // Plain epilogue: bias + fp32 store
        #pragma unroll
        for (int mi = 0; mi < 4; mi++) {
            int row0 = rowBase + wm * 64 + mi * 16 + g;
            int row1 = row0 + 8;
            #pragma unroll
            for (int ni = 0; ni < 4; ni++) {
                int col = colBase + wn * 32 + ni * 8 + tig * 2;
                float b0 = __ldg(&bias[col]);
                float b1 = __ldg(&bias[col + 1]);
                C[(size_t)row0 * Nz + col]     = acc[mi][ni][0] + b0;
                C[(size_t)row0 * Nz + col + 1] = acc[mi][ni][1] + b1;
                C[(size_t)row1 * Nz + col]     = acc[mi][ni][2] + b0;
                C[(size_t)row1 * Nz + col + 1] = acc[mi][ni][3] + b1;
            }
        }
        return;
    }

    // ----- FUSED epilogue (QKV) -----
    #pragma unroll
    for (int ni = 0; ni < 4; ni++) {
        int col = colBase + wn * 32 + ni * 8 + tig * 2;
        float b0 = __ldg(&bias[col]);
        float b1 = __ldg(&bias[col + 1]);
        #pragma unroll
        for (int mi = 0; mi < 4; mi++) {
            acc[mi][ni][0] += b0; acc[mi][ni][1] += b1;
            acc[mi][ni][2] += b0; acc[mi][ni][3] += b1;
        }
    }

    const int sec = colBase >> 10;         // 0=q, 1=k, 2=v
    const int cb  = colBase & 1023;
    const int bb  = rowBase >> 11;         // batch (Sn = 2048)
    const int s0row = rowBase & 2047;

    if (sec < 2) {
        // --- RMSNorm + fp16 split for q/k ---
        float* red = (float*)sm;           // [4 warpsN][128 rows]
        #pragma unroll
        for (int mi = 0; mi < 4; mi++) {
            float l0 = 0.0f, l1 = 0.0f;
            #pragma unroll
            for (int ni = 0; ni < 4; ni++) {
                l0 += acc[mi][ni][0] * acc[mi][ni][0] + acc[mi][ni][1] * acc[mi][ni][1];
                l1 += acc[mi][ni][2] * acc[mi][ni][2] + acc[mi][ni][3] * acc[mi][ni][3];
            }
            l0 += __shfl_xor_sync(0xffffffffu, l0, 1);
            l0 += __shfl_xor_sync(0xffffffffu, l0, 2);
            l1 += __shfl_xor_sync(0xffffffffu, l1, 1);
            l1 += __shfl_xor_sync(0xffffffffu, l1, 2);
            if (tig == 0) {
                int lr = wm * 64 + mi * 16 + g;
                red[wn * 128 + lr]     = l0;
                red[wn * 128 + lr + 8] = l1;
            }
        }
        __syncthreads();

        const float* wv = sec ? wk : wq;
        __half* dh = sec ? g_Kh : g_Qh;
        __half* dl = sec ? g_Kl : g_Ql;
        const int head = (cb >> 6) + (wn >> 1);

        #pragma unroll
        for (int mi = 0; mi < 4; mi++) {
            int lr = wm * 64 + mi * 16 + g;
            float ssq0 = red[wn * 128 + lr]     + red[(wn ^ 1) * 128 + lr];
            float ssq1 = red[wn * 128 + lr + 8] + red[(wn ^ 1) * 128 + lr + 8];
            float inv0 = rsqrtf(ssq0 * (1.0f / DH) + 1e-6f);
            float inv1 = rsqrtf(ssq1 * (1.0f / DH) + 1e-6f);
            size_t row0 = (size_t)(rowBase + lr);
            size_t row1 = row0 + 8;
            #pragma unroll
            for (int ni = 0; ni < 4; ni++) {
                int ic = (wn & 1) * 32 + ni * 8 + tig * 2;
                float wf0 = __ldg(&wv[ic]);
                float wf1 = __ldg(&wv[ic + 1]);
                size_t o0 = row0 * Dn + head * 64 + ic;
                size_t o1 = row1 * Dn + head * 64 + ic;
                __half h0, lo0, h1, lo1;
                split_f16(acc[mi][ni][0] * inv0 * wf0, h0, lo0);
                split_f16(acc[mi][ni][1] * inv0 * wf1, h1, lo1);
                *(unsigned*)&dh[o0] = pack2h(h0, h1);
                *(unsigned*)&dl[o0] = pack2h(lo0, lo1);
                split_f16(acc[mi][ni][2] * inv1 * wf0, h0, lo0);
                split_f16(acc[mi][ni][3] * inv1 * wf1, h1, lo1);
                *(unsigned*)&dh[o1] = pack2h(h0, h1);
                *(unsigned*)&dl[o1] = pack2h(lo0, lo1);
            }
        }
    } else {
        // --- V: transpose via smem, fp16 split, write [d][s] ---
        float (*vt)[129] = (float(*)[129])sm;   // 128 x 129 fp32 = 66048 B
        #pragma unroll
        for (int mi = 0; mi < 4; mi++) {
            int lr0 = wm * 64 + mi * 16 + g;
            #pragma unroll
            for (int ni = 0; ni < 4; ni++) {
                int lc = wn * 32 + ni * 8 + tig * 2;
                vt[lr0][lc]     = acc[mi][ni][0];
                vt[lr0][lc + 1] = acc[mi][ni][1];
                vt[lr0 + 8][lc]     = acc[mi][ni][2];
                vt[lr0 + 8][lc + 1] = acc[mi][ni][3];
            }
        }
        __syncthreads();

        int d  = tid >> 1;               // 0..127
        int sh = (tid & 1) * 64;         // s half
        int hg = (cb >> 6) + (d >> 6);   // global head
        int dl_ = d & 63;
        size_t base = ((size_t)(bb * NH + hg) * DH + dl_) * Sn + s0row + sh;
        #pragma unroll
        for (int i = 0; i < 64; i += 2) {
            float v0 = vt[sh + i][d];
            float v1 = vt[sh + i + 1][d];
            __half h0, l0, h1, l1;
            split_f16(v0, h0, l0);
            split_f16(v1, h1, l1);
            *(unsigned*)&g_Vth[base + i] = pack2h(h0, h1);
            *(unsigned*)&g_Vtl[base + i] = pack2h(l0, l1);
        }
    }
}

// ---------------------------------------------------------------------------
// Flash attention, fp16 mma.sync + ldmatrix, 64-row q tiles.
// QK^T: fp16x3. PV: fp16 P x fp16 hi/lo V (2 MMAs). l-sum reduction deferred
// to a single end-of-loop shuffle (alpha scales are quad-uniform).
// ---------------------------------------------------------------------------
#define AP 36
#define ATILE (64 * AP)
#define ATB (ATILE * 4)                // tile bytes 9216
#define ATTN_SMEM (6 * ATILE * 4)      // 55296 B

__global__ __launch_bounds__(128) void attn_mma_kernel() {
    extern __shared__ unsigned smu[];

    const int tid  = threadIdx.x;
    const int lane = tid & 31;
    const int w    = tid >> 5;
    const int g    = lane >> 2;
    const int tig  = lane & 3;
    const int lane8 = lane & 7;
    const int lb3  = (lane >> 3) & 1;
    const int lb4  = (lane >> 4) & 1;

    const int qt = gridDim.x - 1 - blockIdx.x;
    const int h  = blockIdx.y;
    const int b  = blockIdx.z;

    const size_t rowQ0 = (size_t)b * Sn + qt * 64;
    const size_t qk_off = h * DH;
    const size_t v_row0 = (size_t)(b * NH + h) * DH;

    const unsigned smu_b = (unsigned)__cvta_generic_to_shared(smu);
    const int m0r = w * 16;
    const unsigned q_loff = (unsigned)((m0r + lane8 + lb3 * 8) * 144 + lb4 * 16);
    const unsigned n_loff = (unsigned)((lane8 + lb4 * 8) * 144 + lb3 * 16);

    #pragma unroll
    for (int it = 0; it < 4; it++) {
        int idx = tid + it * 128;
        int r = idx >> 3, q4 = idx & 7;
        const uint4* gh = (const uint4*)(g_Qh + (rowQ0 + r) * Dn + qk_off);
        const uint4* gl = (const uint4*)(g_Ql + (rowQ0 + r) * Dn + qk_off);
        ((uint4*)(smu + r * AP))[q4] = gh[q4];
        ((uint4*)(smu + ATILE + r * AP))[q4] = gl[q4];
    }

    float o[8][4];
    #pragma unroll
    for (int ni = 0; ni < 8; ni++)
        #pragma unroll
        for (int c = 0; c < 4; c++) o[ni][c] = 0.0f;
    float m0 = -INFINITY, m1 = -INFINITY, lp0 = 0.0f, lp1 = 0.0f;

    __syncthreads();

    for (int kt = 0; kt <= qt; kt++) {
        const size_t rowK0 = (size_t)b * Sn + kt * 64;
        #pragma unroll
        for (int it = 0; it < 4; it++) {
            int idx = tid + it * 128;
            int r = idx >> 3, q4 = idx & 7;
            const uint4* kh = (const uint4*)(g_Kh + (rowK0 + r) * Dn + qk_off);
            const uint4* kl = (const uint4*)(g_Kl + (rowK0 + r) * Dn + qk_off);
            ((uint4*)(smu + 2 * ATILE + r * AP))[q4] = kh[q4];
            ((uint4*)(smu + 3 * ATILE + r * AP))[q4] = kl[q4];
            const uint4* vh = (const uint4*)(g_Vth + (v_row0 + r) * Sn + kt * 64);
            const uint4* vl = (const uint4*)(g_Vtl + (v_row0 + r) * Sn + kt * 64);
            ((uint4*)(smu + 4 * ATILE + r * AP))[q4] = vh[q4];
            ((uint4*)(smu + 5 * ATILE + r * AP))[q4] = vl[q4];
        }
        __syncthreads();

        float s[8][4];
        #pragma unroll
        for (int ni = 0; ni < 8; ni++)
            #pragma unroll
            for (int c = 0; c < 4; c++) s[ni][c] = 0.0f;

        #pragma unroll
        for (int kk = 0; kk < 4; kk++) {
            unsigned ah[4], al[4];
            ldsm4(ah[0], ah[1], ah[2], ah[3], smu_b + q_loff + kk * 32);
            ldsm4(al[0], al[1], al[2], al[3], smu_b + ATB + q_loff + kk * 32);
            #pragma unroll
            for (int p = 0; p < 4; p++) {
                unsigned bh[4], bl[4];
                unsigned kd = smu_b + 2 * ATB + n_loff + (unsigned)(p * 16 * 144 + kk * 32);
                ldsm4(bh[0], bh[1], bh[2], bh[3], kd);
                ldsm4(bl[0], bl[1], bl[2], bl[3], kd + ATB);
                mma16816h(s[2*p],   ah, bh);
                mma16816h(s[2*p],   ah, bl);
                mma16816h(s[2*p],   al, bh);
                mma16816h(s[2*p+1], ah, bh + 2);
                mma16816h(s[2*p+1], ah, bl + 2);
                mma16816h(s[2*p+1], al, bh + 2);
            }
        }

        if (kt == qt) {
            #pragma unroll
            for (int ni = 0; ni < 8; ni++) {
                int col = ni * 8 + 2 * tig;
                int r0 = m0r + g, r1 = r0 + 8;
                if (col > r0)     s[ni][0] = -INFINITY;
                if (col + 1 > r0) s[ni][1] = -INFINITY;
                if (col > r1)     s[ni][2] = -INFINITY;
                if (col + 1 > r1) s[ni][3] = -INFINITY;
            }
        }

        float rm0 = -INFINITY, rm1 = -INFINITY;
        #pragma unroll
        for (int ni = 0; ni < 8; ni++) {
            rm0 = fmaxf(rm0, fmaxf(s[ni][0], s[ni][1]));
            rm1 = fmaxf(rm1, fmaxf(s[ni][2], s[ni][3]));
        }
        rm0 = fmaxf(rm0, __shfl_xor_sync(0xffffffffu, rm0, 1));
        rm0 = fmaxf(rm0, __shfl_xor_sync(0xffffffffu, rm0, 2));
        rm1 = fmaxf(rm1, __shfl_xor_sync(0xffffffffu, rm1, 1));
        rm1 = fmaxf(rm1, __shfl_xor_sync(0xffffffffu, rm1, 2));
        float mn0 = fmaxf(m0, rm0), mn1 = fmaxf(m1, rm1);

        float rs0 = 0.0f, rs1 = 0.0f;
        #pragma unroll
        for (int ni = 0; ni < 8; ni++) {
            s[ni][0] = __expf(s[ni][0] - mn0);
            s[ni][1] = __expf(s[ni][1] - mn0);
            s[ni][2] = __expf(s[ni][2] - mn1);
            s[ni][3] = __expf(s[ni][3] - mn1);
            rs0 += s[ni][0] + s[ni][1];
            rs1 += s[ni][2] + s[ni][3];
        }

        float al0 = __expf(m0 - mn0), al1 = __expf(m1 - mn1);
        lp0 = lp0 * al0 + rs0;         // per-thread partial; reduced at end
        lp1 = lp1 * al1 + rs1;
        m0 = mn0; m1 = mn1;
        #pragma unroll
        for (int ni = 0; ni < 8; ni++) {
            o[ni][0] *= al0; o[ni][1] *= al0;
            o[ni][2] *= al1; o[ni][3] *= al1;
        }

        // ---- O += P @ V : P as single fp16, V fp16 hi/lo (2 MMAs) ----
        #pragma unroll
        for (int kk = 0; kk < 4; kk++) {
            unsigned pah[4];
            {
                __half2 p0(__float2half_rn(s[2*kk][0]),   __float2half_rn(s[2*kk][1]));
                __half2 p1(__float2half_rn(s[2*kk][2]),   __float2half_rn(s[2*kk][3]));
                __half2 p2(__float2half_rn(s[2*kk+1][0]), __float2half_rn(s[2*kk+1][1]));
                __half2 p3(__float2half_rn(s[2*kk+1][2]), __float2half_rn(s[2*kk+1][3]));
                pah[0] = *(unsigned*)&p0;
                pah[1] = *(unsigned*)&p1;
                pah[2] = *(unsigned*)&p2;
                pah[3] = *(unsigned*)&p3;
            }
            #pragma unroll
            for (int p = 0; p < 4; p++) {
                unsigned vh[4], vl[4];
                unsigned vd = smu_b + 4 * ATB + n_loff + (unsigned)(p * 16 * 144 + kk * 32);
                ldsm4(vh[0], vh[1], vh[2], vh[3], vd);
                ldsm4(vl[0], vl[1], vl[2], vl[3], vd + ATB);
                mma16816h(o[2*p],   pah, vh);
                mma16816h(o[2*p],   pah, vl);
                mma16816h(o[2*p+1], pah, vh + 2);
                mma16816h(o[2*p+1], pah, vl + 2);
            }
        }
        __syncthreads();
    }

    // final l reduction across the quad (alpha history was quad-uniform)
    lp0 += __shfl_xor_sync(0xffffffffu, lp0, 1);
    lp0 += __shfl_xor_sync(0xffffffffu, lp0, 2);
    lp1 += __shfl_xor_sync(0xffffffffu, lp1, 1);
    lp1 += __shfl_xor_sync(0xffffffffu, lp1, 2);

    float inv0 = 1.0f / lp0, inv1 = 1.0f / lp1;
    size_t row0 = rowQ0 + w * 16 + g;
    size_t row1 = row0 + 8;
    #pragma unroll
    for (int ni = 0; ni < 8; ni++) {
        int col = h * DH + ni * 8 + 2 * tig;
        __half2 z0(__float2half_rn(o[ni][0] * inv0), __float2half_rn(o[ni][1] * inv0));
        __half2 z1(__float2half_rn(o[ni][2] * inv1), __float2half_rn(o[ni][3] * inv1));
        *(__half2*)&g_Ah[row0 * Dn + col] = z0;
        *(__half2*)&g_Ah[row1 * Dn + col] = z1;
    }
}

// ---------------------------------------------------------------------------
extern "C" void kernel_launch(void* const* d_in, const int* in_sizes, int n_in,
                              void* d_out, int out_size) {
    const float* x     = (const float*)d_in[0];
    const float* W_qkv = (const float*)d_in[2];
    const float* b_qkv = (const float*)d_in[3];
    const float* W_o   = (const float*)d_in[4];
    const float* b_o   = (const float*)d_in[5];
    const float* wq    = (const float*)d_in[6];
    const float* wk    = (const float*)d_in[7];
    float* out = (float*)d_out;

    void *ah, *wth, *wtl, *woth;
    cudaGetSymbolAddress(&ah, g_Ah);
    cudaGetSymbolAddress(&wth, g_Wth);
    cudaGetSymbolAddress(&wtl, g_Wtl);
    cudaGetSymbolAddress(&woth, g_Woth);

    cudaFuncSetAttribute(gemm_f16x2<1>,
                         cudaFuncAttributeMaxDynamicSharedMemorySize, GEMM_SMEM);
    cudaFuncSetAttribute(gemm_f16x2<0>,
                         cudaFuncAttributeMaxDynamicSharedMemorySize, GEMM_SMEM);
    cudaFuncSetAttribute(attn_mma_kernel,
                         cudaFuncAttributeMaxDynamicSharedMemorySize, ATTN_SMEM);

    // 0) Preprocessing: x -> fp16; W_qkv -> hi/lo transpose; W_o -> hi only
    cvt_f16_kernel<<<1024, 256>>>(x, (__half*)ah, (size_t)Mrows * Dn / 4);
    {
        dim3 grid(N3 / 32, Dn / 32);
        tsplit_f16_kernel<<<grid, dim3(32, 8)>>>(W_qkv, (__half*)wth,
                                                 (__half*)wtl, Dn, N3);
    }
    {
        dim3 grid(Dn / 32, Dn / 32);
        tsplit_f16_kernel<<<grid, dim3(32, 8)>>>(W_o, (__half*)woth,
                                                 nullptr, Dn, Dn);
    }

    // 1) QKV GEMM (fp16x2 on q/k, fp16 on v) + fused rmsnorm/v-transpose
    {
        dim3 grid(N3 / 128, Mrows / 128);
        gemm_f16x2<1><<<grid, 256, GEMM_SMEM>>>(
            (const __half*)ah, (const __half*)wth, (const __half*)wtl,
            b_qkv, nullptr, wq, wk, N3, Dn);
    }

    // 2) Flash attention — writes fp16 z into g_Ah
    {
        dim3 grid(Sn / 64, NH, Bn);
        attn_mma_kernel<<<grid, 128, ATTN_SMEM>>>();
    }

    // 3) Output projection (single-term fp16 W)
    {
        dim3 grid(Dn / 128, Mrows / 128);
        gemm_f16x2<0><<<grid, 256, GEMM_SMEM>>>(
            (const __half*)ah, (const __half*)woth, nullptr,
            b_o, out, nullptr, nullptr, Dn, Dn);
    }
}

// round 16
// speedup vs baseline: 1.1996x; 1.0443x over previous
#include <cuda_runtime.h>
#include <cuda_bf16.h>
#include <cuda_fp16.h>
#include <math.h>
#include <stdint.h>

#define Bn 4
#define Sn 2048
#define Dn 1024
#define NH 16
#define DH 64
#define Mrows (Bn*Sn)      // 8192
#define N3 (3*Dn)          // 3072

// Scratch (device globals: allocation-free per harness rules)
__device__ __half g_Ah[(size_t)Mrows * Dn];            // fp16(x) / fp16(attn out)
__device__ __half g_Wth[(size_t)N3 * Dn];              // W_qkv^T hi [N][K]
__device__ __half g_Wtl[(size_t)N3 * Dn];              // W_qkv^T lo
__device__ __half g_Woth[(size_t)Dn * Dn];             // W_o^T (fp16 single)
__device__ __half g_Qh[(size_t)Mrows * Dn];            // rmsnormed q split (fp16)
__device__ __half g_Ql[(size_t)Mrows * Dn];
__device__ __half g_Kh[(size_t)Mrows * Dn];
__device__ __half g_Kl[(size_t)Mrows * Dn];
__device__ __half g_Vth[(size_t)Mrows * Dn];           // V^T split: [(b*NH+h)*DH+d][s]
__device__ __half g_Vtl[(size_t)Mrows * Dn];

__device__ __forceinline__ void split_f16(float x, __half& h, __half& l) {
    h = __float2half_rn(x);
    l = __float2half_rn(x - __half2float(h));
}
__device__ __forceinline__ unsigned pack2h(__half lo, __half hi) {
    __half2 p(lo, hi);
    return *(unsigned*)&p;
}
__device__ __forceinline__ void mma16816h(float* c, const unsigned* a, const unsigned* b) {
    asm volatile(
        "mma.sync.aligned.m16n8k16.row.col.f32.f16.f16.f32 "
        "{%0,%1,%2,%3}, {%4,%5,%6,%7}, {%8,%9}, {%0,%1,%2,%3};"
        : "+f"(c[0]), "+f"(c[1]), "+f"(c[2]), "+f"(c[3])
        : "r"(a[0]), "r"(a[1]), "r"(a[2]), "r"(a[3]), "r"(b[0]), "r"(b[1]));
}
__device__ __forceinline__ void cp16(unsigned smem_addr, const void* gptr) {
    asm volatile("cp.async.cg.shared.global [%0], [%1], 16;"
                 :: "r"(smem_addr), "l"(gptr));
}
__device__ __forceinline__ void ldsm4(unsigned& r0, unsigned& r1,
                                      unsigned& r2, unsigned& r3, unsigned addr) {
    asm volatile("ldmatrix.sync.aligned.m8n8.x4.shared.b16 {%0,%1,%2,%3}, [%4];"
                 : "=r"(r0), "=r"(r1), "=r"(r2), "=r"(r3) : "r"(addr));
}

// ---------------------------------------------------------------------------
// fp32 -> fp16 convert (for x)
// ---------------------------------------------------------------------------
__global__ void cvt_f16_kernel(const float* __restrict__ in,
                               __half* __restrict__ out, size_t n4) {
    size_t i = (size_t)blockIdx.x * blockDim.x + threadIdx.x;
    size_t stride = (size_t)gridDim.x * blockDim.x;
    for (; i < n4; i += stride) {
        float4 v = ((const float4*)in)[i];
        __half2 a(__float2half_rn(v.x), __float2half_rn(v.y));
        __half2 b(__float2half_rn(v.z), __float2half_rn(v.w));
        ((__half2*)out)[i * 2]     = a;
        ((__half2*)out)[i * 2 + 1] = b;
    }
}

// ---------------------------------------------------------------------------
// Transpose + fp16 split: W[K][N] fp32 -> Wt hi (and optionally lo) [N][K]
// ---------------------------------------------------------------------------
__global__ void tsplit_f16_kernel(const float* __restrict__ W,
                                  __half* __restrict__ th,
                                  __half* __restrict__ tl, int K, int N) {
    __shared__ float t[32][33];
    int n0 = blockIdx.x * 32, k0 = blockIdx.y * 32;
    int tx = threadIdx.x, ty = threadIdx.y;           // (32, 8)
    #pragma unroll
    for (int i = ty; i < 32; i += 8)
        t[i][tx] = W[(size_t)(k0 + i) * N + n0 + tx];
    __syncthreads();
    #pragma unroll
    for (int i = ty; i < 32; i += 8) {
        float v = t[tx][i];
        __half h, l;
        split_f16(v, h, l);
        th[(size_t)(n0 + i) * K + k0 + tx] = h;
        if (tl) tl[(size_t)(n0 + i) * K + k0 + tx] = l;
    }
}

// ---------------------------------------------------------------------------
// fp16 triple-buffered cp.async GEMM (round-15 verified, unchanged).
// ---------------------------------------------------------------------------
#define BKK 32
#define PITCH 20                       // 16 data u32 + 4 pad (5x16B, coprime 8)
#define TILE_U32 (128 * PITCH)
#define TILEB (TILE_U32 * 4)
#define STAGE_U32 (3 * TILE_U32)       // A, Bh, Bl
#define GEMM_SMEM (3 * STAGE_U32 * 4)  // 3 stages = 92160 B (>= 128*129*4 transpose)

template<int FUSED>
__global__ __launch_bounds__(256, 2)
void gemm_f16x2(const __half* __restrict__ A,
                const __half* __restrict__ Bth,
                const __half* __restrict__ Btl,
                const float* __restrict__ bias,
                float* __restrict__ C,
                const float* __restrict__ wq,
                const float* __restrict__ wk,
                int Nz, int Kz) {
    extern __shared__ unsigned sm[];

    const int tid  = threadIdx.x;
    const int lane = tid & 31;
    const int wid  = tid >> 5;
    const int wm   = wid >> 2;
    const int wn   = wid & 3;
    const int g    = lane >> 2;
    const int tig  = lane & 3;
    const int lane8 = lane & 7;
    const int lb3  = (lane >> 3) & 1;
    const int lb4  = (lane >> 4) & 1;

    const int rowBase = blockIdx.y * 128;
    const int colBase = blockIdx.x * 128;
    const bool use_lo = FUSED ? (colBase < 2048) : false;

    const int r0 = tid >> 2;
    const int c4 = tid & 3;

    const unsigned smem_base = (unsigned)__cvta_generic_to_shared(sm);

    const unsigned a_off = (unsigned)((wm * 64 + lane8 + lb3 * 8) * 80 + lb4 * 16);
    const unsigned b_off = (unsigned)((wn * 32 + lane8 + lb4 * 8) * 80 + lb3 * 16);

    float acc[4][4][4];
    #pragma unroll
    for (int i = 0; i < 4; i++)
        #pragma unroll
        for (int j = 0; j < 4; j++)
            #pragma unroll
            for (int q = 0; q < 4; q++) acc[i][j][q] = 0.0f;

    const int NIT = Kz / BKK;

    auto load_stage = [&](int it, int buf) {
        const int k0 = it * BKK;
        const unsigned sbase = smem_base + buf * STAGE_U32 * 4;
        #pragma unroll
        for (int it2 = 0; it2 < 2; it2++) {
            int row = r0 + it2 * 64;
            unsigned soff = (unsigned)(row * PITCH + c4 * 4) * 4;
            const __half* gA  = A   + (size_t)(rowBase + row) * Kz + k0 + c4 * 8;
            const __half* gBh = Bth + (size_t)(colBase + row) * Kz + k0 + c4 * 8;
            cp16(sbase + soff, gA);
            cp16(sbase + TILEB + soff, gBh);
            if (use_lo) {
                const __half* gBl = Btl + (size_t)(colBase + row) * Kz + k0 + c4 * 8;
                cp16(sbase + 2 * TILEB + soff, gBl);
            }
        }
        asm volatile("cp.async.commit_group;");
    };

    load_stage(0, 0);
    load_stage(1, 1);

    for (int it = 0; it < NIT; it++) {
        const int buf = it % 3;
        if (it + 2 < NIT) {
            load_stage(it + 2, (it + 2) % 3);
            asm volatile("cp.async.wait_group 2;");
        } else if (it + 1 < NIT) {
            asm volatile("cp.async.wait_group 1;");
        } else {
            asm volatile("cp.async.wait_group 0;");
        }
        __syncthreads();

        const unsigned stg = smem_base + buf * STAGE_U32 * 4;

        #pragma unroll
        for (int kk8 = 0; kk8 < 2; kk8++) {
            unsigned a[4][4], bhi[4][2], blo[4][2];
            #pragma unroll
            for (int mi = 0; mi < 4; mi++) {
                unsigned ad = stg + a_off + (unsigned)(mi * 16 * 80 + kk8 * 32);
                ldsm4(a[mi][0], a[mi][1], a[mi][2], a[mi][3], ad);
            }
            #pragma unroll
            for (int p = 0; p < 2; p++) {
                unsigned bd = stg + TILEB + b_off + (unsigned)(p * 16 * 80 + kk8 * 32);
                ldsm4(bhi[2*p][0], bhi[2*p][1], bhi[2*p+1][0], bhi[2*p+1][1], bd);
            }
            if (use_lo) {
                #pragma unroll
                for (int p = 0; p < 2; p++) {
                    unsigned bd = stg + 2 * TILEB + b_off + (unsigned)(p * 16 * 80 + kk8 * 32);
                    ldsm4(blo[2*p][0], blo[2*p][1], blo[2*p+1][0], blo[2*p+1][1], bd);
                }
            }
            #pragma unroll
            for (int mi = 0; mi < 4; mi++)
                #pragma unroll
                for (int ni = 0; ni < 4; ni++) {
                    mma16816h(acc[mi][ni], a[mi], bhi[ni]);
                    if (use_lo) mma16816h(acc[mi][ni], a[mi], blo[ni]);
                }
        }
        __syncthreads();
    }

    if (!FUSED) {
        #pragma unroll
        for (int mi = 0; mi < 4; mi++) {
            int row0 = rowBase + wm * 64 + mi * 16 + g;
            int row1 = row0 + 8;
            #pragma unroll
            for (int ni = 0; ni < 4; ni++) {
                int col = colBase + wn * 32 + ni * 8 + tig * 2;
                float b0 = __ldg(&bias[col]);
                float b1 = __ldg(&bias[col + 1]);
                C[(size_t)row0 * Nz + col]     = acc[mi][ni][0] + b0;
                C[(size_t)row0 * Nz + col + 1] = acc[mi][ni][1] + b1;
                C[(size_t)row1 * Nz + col]     = acc[mi][ni][2] + b0;
                C[(size_t)row1 * Nz + col + 1] = acc[mi][ni][3] + b1;
            }
        }
        return;
    }

    // ----- FUSED epilogue (QKV) -----
    #pragma unroll
    for (int ni = 0; ni < 4; ni++) {
        int col = colBase + wn * 32 + ni * 8 + tig * 2;
        float b0 = __ldg(&bias[col]);
        float b1 = __ldg(&bias[col + 1]);
        #pragma unroll
        for (int mi = 0; mi < 4; mi++) {
            acc[mi][ni][0] += b0; acc[mi][ni][1] += b1;
            acc[mi][ni][2] += b0; acc[mi][ni][3] += b1;
        }
    }

    const int sec = colBase >> 10;         // 0=q, 1=k, 2=v
    const int cb  = colBase & 1023;
    const int bb  = rowBase >> 11;         // batch (Sn = 2048)
    const int s0row = rowBase & 2047;

    if (sec < 2) {
        float* red = (float*)sm;
        #pragma unroll
        for (int mi = 0; mi < 4; mi++) {
            float l0 = 0.0f, l1 = 0.0f;
            #pragma unroll
            for (int ni = 0; ni < 4; ni++) {
                l0 += acc[mi][ni][0] * acc[mi][ni][0] + acc[mi][ni][1] * acc[mi][ni][1];
                l1 += acc[mi][ni][2] * acc[mi][ni][2] + acc[mi][ni][3] * acc[mi][ni][3];
            }
            l0 += __shfl_xor_sync(0xffffffffu, l0, 1);
            l0 += __shfl_xor_sync(0xffffffffu, l0, 2);
            l1 += __shfl_xor_sync(0xffffffffu, l1, 1);
            l1 += __shfl_xor_sync(0xffffffffu, l1, 2);
            if (tig == 0) {
                int lr = wm * 64 + mi * 16 + g;
                red[wn * 128 + lr]     = l0;
                red[wn * 128 + lr + 8] = l1;
            }
        }
        __syncthreads();

        const float* wv = sec ? wk : wq;
        __half* dh = sec ? g_Kh : g_Qh;
        __half* dl = sec ? g_Kl : g_Ql;
        const int head = (cb >> 6) + (wn >> 1);

        #pragma unroll
        for (int mi = 0; mi < 4; mi++) {
            int lr = wm * 64 + mi * 16 + g;
            float ssq0 = red[wn * 128 + lr]     + red[(wn ^ 1) * 128 + lr];
            float ssq1 = red[wn * 128 + lr + 8] + red[(wn ^ 1) * 128 + lr + 8];
            float inv0 = rsqrtf(ssq0 * (1.0f / DH) + 1e-6f);
            float inv1 = rsqrtf(ssq1 * (1.0f / DH) + 1e-6f);
            size_t row0 = (size_t)(rowBase + lr);
            size_t row1 = row0 + 8;
            #pragma unroll
            for (int ni = 0; ni < 4; ni++) {
                int ic = (wn & 1) * 32 + ni * 8 + tig * 2;
                float wf0 = __ldg(&wv[ic]);
                float wf1 = __ldg(&wv[ic + 1]);
                size_t o0 = row0 * Dn + head * 64 + ic;
                size_t o1 = row1 * Dn + head * 64 + ic;
                __half h0, lo0, h1, lo1;
                split_f16(acc[mi][ni][0] * inv0 * wf0, h0, lo0);
                split_f16(acc[mi][ni][1] * inv0 * wf1, h1, lo1);
                *(unsigned*)&dh[o0] = pack2h(h0, h1);
                *(unsigned*)&dl[o0] = pack2h(lo0, lo1);
                split_f16(acc[mi][ni][2] * inv1 * wf0, h0, lo0);
                split_f16(acc[mi][ni][3] * inv1 * wf1, h1, lo1);
                *(unsigned*)&dh[o1] = pack2h(h0, h1);
                *(unsigned*)&dl[o1] = pack2h(lo0, lo1);
            }
        }
    } else {
        float (*vt)[129] = (float(*)[129])sm;
        #pragma unroll
        for (int mi = 0; mi < 4; mi++) {
            int lr0 = wm * 64 + mi * 16 + g;
            #pragma unroll
            for (int ni = 0; ni < 4; ni++) {
                int lc = wn * 32 + ni * 8 + tig * 2;
                vt[lr0][lc]     = acc[mi][ni][0];
                vt[lr0][lc + 1] = acc[mi][ni][1];
                vt[lr0 + 8][lc]     = acc[mi][ni][2];
                vt[lr0 + 8][lc + 1] = acc[mi][ni][3];
            }
        }
        __syncthreads();

        int d  = tid >> 1;
        int sh = (tid & 1) * 64;
        int hg = (cb >> 6) + (d >> 6);
        int dl_ = d & 63;
        size_t base = ((size_t)(bb * NH + hg) * DH + dl_) * Sn + s0row + sh;
        #pragma unroll
        for (int i = 0; i < 64; i += 2) {
            float v0 = vt[sh + i][d];
            float v1 = vt[sh + i + 1][d];
            __half h0, l0, h1, l1;
            split_f16(v0, h0, l0);
            split_f16(v1, h1, l1);
            *(unsigned*)&g_Vth[base + i] = pack2h(h0, h1);
            *(unsigned*)&g_Vtl[base + i] = pack2h(l0, l1);
        }
    }
}

// ---------------------------------------------------------------------------
// Flash attention: Q fragments in registers, cp.async double-buffered K/V.
// QK^T fp16x3, PV fp16 P x fp16 hi/lo V (numerics identical to round 15).
// Smem: 2 stages x (Kh,Kl,Vh,Vl) = 8 ATILE = 73728 B; 3 CTAs/SM.
// ---------------------------------------------------------------------------
#define AP 36
#define ATILE (64 * AP)
#define ATB (ATILE * 4)                // tile bytes 9216
#define ATTN_SMEM (8 * ATILE * 4)      // 73728 B

__global__ __launch_bounds__(128, 3) void attn_mma_kernel() {
    extern __shared__ unsigned smu[];

    const int tid  = threadIdx.x;
    const int lane = tid & 31;
    const int w    = tid >> 5;
    const int g    = lane >> 2;
    const int tig  = lane & 3;
    const int lane8 = lane & 7;
    const int lb3  = (lane >> 3) & 1;
    const int lb4  = (lane >> 4) & 1;

    const int qt = gridDim.x - 1 - blockIdx.x;
    const int h  = blockIdx.y;
    const int b  = blockIdx.z;

    const size_t rowQ0 = (size_t)b * Sn + qt * 64;
    const size_t qk_off = h * DH;
    const size_t v_row0 = (size_t)(b * NH + h) * DH;

    const unsigned smu_b = (unsigned)__cvta_generic_to_shared(smu);
    const int m0r = w * 16;
    const unsigned q_loff = (unsigned)((m0r + lane8 + lb3 * 8) * 144 + lb4 * 16);
    const unsigned n_loff = (unsigned)((lane8 + lb4 * 8) * 144 + lb3 * 16);

    // ---- Stage Q into stage-0 area, extract fragments to registers ----
    #pragma unroll
    for (int it = 0; it < 4; it++) {
        int idx = tid + it * 128;
        int r = idx >> 3, q4 = idx & 7;
        const uint4* gh = (const uint4*)(g_Qh + (rowQ0 + r) * Dn + qk_off);
        const uint4* gl = (const uint4*)(g_Ql + (rowQ0 + r) * Dn + qk_off);
        ((uint4*)(smu + r * AP))[q4] = gh[q4];
        ((uint4*)(smu + ATILE + r * AP))[q4] = gl[q4];
    }
    __syncthreads();
    unsigned qah[4][4], qal[4][4];
    #pragma unroll
    for (int kk = 0; kk < 4; kk++) {
        ldsm4(qah[kk][0], qah[kk][1], qah[kk][2], qah[kk][3],
              smu_b + q_loff + kk * 32);
        ldsm4(qal[kk][0], qal[kk][1], qal[kk][2], qal[kk][3],
              smu_b + ATB + q_loff + kk * 32);
    }
    __syncthreads();   // staging area free for the K/V pipeline

    float o[8][4];
    #pragma unroll
    for (int ni = 0; ni < 8; ni++)
        #pragma unroll
        for (int c = 0; c < 4; c++) o[ni][c] = 0.0f;
    float m0 = -INFINITY, m1 = -INFINITY, lp0 = 0.0f, lp1 = 0.0f;

    // K/V pipeline: stage s base = s * 4 * ATB; tiles Kh,Kl,Vh,Vl
    auto load_kv = [&](int kt, int s) {
        const size_t rowK0 = (size_t)b * Sn + kt * 64;
        const unsigned sb = smu_b + (unsigned)(s * 4 * ATB);
        #pragma unroll
        for (int it = 0; it < 4; it++) {
            int idx = tid + it * 128;
            int r = idx >> 3, q4 = idx & 7;
            unsigned soff = (unsigned)(r * 144 + q4 * 16);
            cp16(sb + soff,           g_Kh  + (rowK0 + r) * Dn + qk_off + q4 * 8);
            cp16(sb + ATB + soff,     g_Kl  + (rowK0 + r) * Dn + qk_off + q4 * 8);
            cp16(sb + 2 * ATB + soff, g_Vth + (v_row0 + r) * Sn + kt * 64 + q4 * 8);
            cp16(sb + 3 * ATB + soff, g_Vtl + (v_row0 + r) * Sn + kt * 64 + q4 * 8);
        }
        asm volatile("cp.async.commit_group;");
    };

    load_kv(0, 0);

    for (int kt = 0; kt <= qt; kt++) {
        const int s = kt & 1;
        if (kt < qt) {
            load_kv(kt + 1, s ^ 1);
            asm volatile("cp.async.wait_group 1;");
        } else {
            asm volatile("cp.async.wait_group 0;");
        }
        __syncthreads();

        const unsigned kvb = smu_b + (unsigned)(s * 4 * ATB);

        float sc[8][4];
        #pragma unroll
        for (int ni = 0; ni < 8; ni++)
            #pragma unroll
            for (int c = 0; c < 4; c++) sc[ni][c] = 0.0f;

        #pragma unroll
        for (int kk = 0; kk < 4; kk++) {
            #pragma unroll
            for (int p = 0; p < 4; p++) {
                unsigned bh[4], bl[4];
                unsigned kd = kvb + n_loff + (unsigned)(p * 16 * 144 + kk * 32);
                ldsm4(bh[0], bh[1], bh[2], bh[3], kd);
                ldsm4(bl[0], bl[1], bl[2], bl[3], kd + ATB);
                mma16816h(sc[2*p],   qah[kk], bh);
                mma16816h(sc[2*p],   qah[kk], bl);
                mma16816h(sc[2*p],   qal[kk], bh);
                mma16816h(sc[2*p+1], qah[kk], bh + 2);
                mma16816h(sc[2*p+1], qah[kk], bl + 2);
                mma16816h(sc[2*p+1], qal[kk], bh + 2);
            }
        }

        if (kt == qt) {
            #pragma unroll
            for (int ni = 0; ni < 8; ni++) {
                int col = ni * 8 + 2 * tig;
                int r0 = m0r + g, r1 = r0 + 8;
                if (col > r0)     sc[ni][0] = -INFINITY;
                if (col + 1 > r0) sc[ni][1] = -INFINITY;
                if (col > r1)     sc[ni][2] = -INFINITY;
                if (col + 1 > r1) sc[ni][3] = -INFINITY;
            }
        }

        float rm0 = -INFINITY, rm1 = -INFINITY;
        #pragma unroll
        for (int ni = 0; ni < 8; ni++) {
            rm0 = fmaxf(rm0, fmaxf(sc[ni][0], sc[ni][1]));
            rm1 = fmaxf(rm1, fmaxf(sc[ni][2], sc[ni][3]));
        }
        rm0 = fmaxf(rm0, __shfl_xor_sync(0xffffffffu, rm0, 1));
        rm0 = fmaxf(rm0, __shfl_xor_sync(0xffffffffu, rm0, 2));
        rm1 = fmaxf(rm1, __shfl_xor_sync(0xffffffffu, rm1, 1));
        rm1 = fmaxf(rm1, __shfl_xor_sync(0xffffffffu, rm1, 2));
        float mn0 = fmaxf(m0, rm0), mn1 = fmaxf(m1, rm1);

        float rs0 = 0.0f, rs1 = 0.0f;
        #pragma unroll
        for (int ni = 0; ni < 8; ni++) {
            sc[ni][0] = __expf(sc[ni][0] - mn0);
            sc[ni][1] = __expf(sc[ni][1] - mn0);
            sc[ni][2] = __expf(sc[ni][2] - mn1);
            sc[ni][3] = __expf(sc[ni][3] - mn1);
            rs0 += sc[ni][0] + sc[ni][1];
            rs1 += sc[ni][2] + sc[ni][3];
        }

        float al0 = __expf(m0 - mn0), al1 = __expf(m1 - mn1);
        lp0 = lp0 * al0 + rs0;
        lp1 = lp1 * al1 + rs1;
        m0 = mn0; m1 = mn1;
        #pragma unroll
        for (int ni = 0; ni < 8; ni++) {
            o[ni][0] *= al0; o[ni][1] *= al0;
            o[ni][2] *= al1; o[ni][3] *= al1;
        }

        // ---- O += P @ V : P single fp16, V fp16 hi/lo (2 MMAs) ----
        #pragma unroll
        for (int kk = 0; kk < 4; kk++) {
            unsigned pah[4];
            {
                __half2 p0(__float2half_rn(sc[2*kk][0]),   __float2half_rn(sc[2*kk][1]));
                __half2 p1(__float2half_rn(sc[2*kk][2]),   __float2half_rn(sc[2*kk][3]));
                __half2 p2(__float2half_rn(sc[2*kk+1][0]), __float2half_rn(sc[2*kk+1][1]));
                __half2 p3(__float2half_rn(sc[2*kk+1][2]), __float2half_rn(sc[2*kk+1][3]));
                pah[0] = *(unsigned*)&p0;
                pah[1] = *(unsigned*)&p1;
                pah[2] = *(unsigned*)&p2;
                pah[3] = *(unsigned*)&p3;
            }
            #pragma unroll
            for (int p = 0; p < 4; p++) {
                unsigned vh[4], vl[4];
                unsigned vd = kvb + 2 * ATB + n_loff + (unsigned)(p * 16 * 144 + kk * 32);
                ldsm4(vh[0], vh[1], vh[2], vh[3], vd);
                ldsm4(vl[0], vl[1], vl[2], vl[3], vd + ATB);
                mma16816h(o[2*p],   pah, vh);
                mma16816h(o[2*p],   pah, vl);
                mma16816h(o[2*p+1], pah, vh + 2);
                mma16816h(o[2*p+1], pah, vl + 2);
            }
        }
        __syncthreads();
    }

    lp0 += __shfl_xor_sync(0xffffffffu, lp0, 1);
    lp0 += __shfl_xor_sync(0xffffffffu, lp0, 2);
    lp1 += __shfl_xor_sync(0xffffffffu, lp1, 1);
    lp1 += __shfl_xor_sync(0xffffffffu, lp1, 2);

    float inv0 = 1.0f / lp0, inv1 = 1.0f / lp1;
    size_t row0 = rowQ0 + w * 16 + g;
    size_t row1 = row0 + 8;
    #pragma unroll
    for (int ni = 0; ni < 8; ni++) {
        int col = h * DH + ni * 8 + 2 * tig;
        __half2 z0(__float2half_rn(o[ni][0] * inv0), __float2half_rn(o[ni][1] * inv0));
        __half2 z1(__float2half_rn(o[ni][2] * inv1), __float2half_rn(o[ni][3] * inv1));
        *(__half2*)&g_Ah[row0 * Dn + col] = z0;
        *(__half2*)&g_Ah[row1 * Dn + col] = z1;
    }
}

// ---------------------------------------------------------------------------
extern "C" void kernel_launch(void* const* d_in, const int* in_sizes, int n_in,
                              void* d_out, int out_size) {
    const float* x     = (const float*)d_in[0];
    const float* W_qkv = (const float*)d_in[2];
    const float* b_qkv = (const float*)d_in[3];
    const float* W_o   = (const float*)d_in[4];
    const float* b_o   = (const float*)d_in[5];
    const float* wq    = (const float*)d_in[6];
    const float* wk    = (const float*)d_in[7];
    float* out = (float*)d_out;

    void *ah, *wth, *wtl, *woth;
    cudaGetSymbolAddress(&ah, g_Ah);
    cudaGetSymbolAddress(&wth, g_Wth);
    cudaGetSymbolAddress(&wtl, g_Wtl);
    cudaGetSymbolAddress(&woth, g_Woth);

    cudaFuncSetAttribute(gemm_f16x2<1>,
                         cudaFuncAttributeMaxDynamicSharedMemorySize, GEMM_SMEM);
    cudaFuncSetAttribute(gemm_f16x2<0>,
                         cudaFuncAttributeMaxDynamicSharedMemorySize, GEMM_SMEM);
    cudaFuncSetAttribute(attn_mma_kernel,
                         cudaFuncAttributeMaxDynamicSharedMemorySize, ATTN_SMEM);

    // 0) Preprocessing: x -> fp16; W_qkv -> hi/lo transpose; W_o -> hi only
    cvt_f16_kernel<<<1024, 256>>>(x, (__half*)ah, (size_t)Mrows * Dn / 4);
    {
        dim3 grid(N3 / 32, Dn / 32);
        tsplit_f16_kernel<<<grid, dim3(32, 8)>>>(W_qkv, (__half*)wth,
                                                 (__half*)wtl, Dn, N3);
    }
    {
        dim3 grid(Dn / 32, Dn / 32);
        tsplit_f16_kernel<<<grid, dim3(32, 8)>>>(W_o, (__half*)woth,
                                                 nullptr, Dn, Dn);
    }

    // 1) QKV GEMM (fp16x2 on q/k, fp16 on v) + fused rmsnorm/v-transpose
    {
        dim3 grid(N3 / 128, Mrows / 128);
        gemm_f16x2<1><<<grid, 256, GEMM_SMEM>>>(
            (const __half*)ah, (const __half*)wth, (const __half*)wtl,
            b_qkv, nullptr, wq, wk, N3, Dn);
    }

    // 2) Flash attention (Q-in-regs + cp.async K/V pipeline)
    {
        dim3 grid(Sn / 64, NH, Bn);
        attn_mma_kernel<<<grid, 128, ATTN_SMEM>>>();
    }

    // 3) Output projection (single-term fp16 W)
    {
        dim3 grid(Dn / 128, Mrows / 128);
        gemm_f16x2<0><<<grid, 256, GEMM_SMEM>>>(
            (const __half*)ah, (const __half*)woth, nullptr,
            b_o, out, nullptr, nullptr, Dn, Dn);
    }
}

// round 17
// speedup vs baseline: 1.3239x; 1.1037x over previous
#include <cuda_runtime.h>
#include <cuda_bf16.h>
#include <cuda_fp16.h>
#include <math.h>
#include <stdint.h>

#define Bn 4
#define Sn 2048
#define Dn 1024
#define NH 16
#define DH 64
#define Mrows (Bn*Sn)      // 8192
#define N3 (3*Dn)          // 3072

// Scratch (device globals: allocation-free per harness rules)
__device__ __half g_Ah[(size_t)Mrows * Dn];            // fp16(x) / fp16(attn out)
__device__ __half g_Wth[(size_t)N3 * Dn];              // W_qkv^T hi [N][K]
__device__ __half g_Wtl[(size_t)N3 * Dn];              // W_qkv^T lo
__device__ __half g_Woth[(size_t)Dn * Dn];             // W_o^T (fp16 single)
__device__ __half g_Qh[(size_t)Mrows * Dn];            // rmsnormed q split (fp16)
__device__ __half g_Ql[(size_t)Mrows * Dn];
__device__ __half g_Kh[(size_t)Mrows * Dn];
__device__ __half g_Kl[(size_t)Mrows * Dn];
__device__ __half g_Vh[(size_t)Mrows * Dn];            // v split, [row][Dn] (K-like)
__device__ __half g_Vl[(size_t)Mrows * Dn];

__device__ __forceinline__ void split_f16(float x, __half& h, __half& l) {
    h = __float2half_rn(x);
    l = __float2half_rn(x - __half2float(h));
}
__device__ __forceinline__ unsigned pack2h(__half lo, __half hi) {
    __half2 p(lo, hi);
    return *(unsigned*)&p;
}
__device__ __forceinline__ void mma16816h(float* c, const unsigned* a, const unsigned* b) {
    asm volatile(
        "mma.sync.aligned.m16n8k16.row.col.f32.f16.f16.f32 "
        "{%0,%1,%2,%3}, {%4,%5,%6,%7}, {%8,%9}, {%0,%1,%2,%3};"
        : "+f"(c[0]), "+f"(c[1]), "+f"(c[2]), "+f"(c[3])
        : "r"(a[0]), "r"(a[1]), "r"(a[2]), "r"(a[3]), "r"(b[0]), "r"(b[1]));
}
__device__ __forceinline__ void cp16(unsigned smem_addr, const void* gptr) {
    asm volatile("cp.async.cg.shared.global [%0], [%1], 16;"
                 :: "r"(smem_addr), "l"(gptr));
}
__device__ __forceinline__ void ldsm4(unsigned& r0, unsigned& r1,
                                      unsigned& r2, unsigned& r3, unsigned addr) {
    asm volatile("ldmatrix.sync.aligned.m8n8.x4.shared.b16 {%0,%1,%2,%3}, [%4];"
                 : "=r"(r0), "=r"(r1), "=r"(r2), "=r"(r3) : "r"(addr));
}
__device__ __forceinline__ void ldsm4t(unsigned& r0, unsigned& r1,
                                       unsigned& r2, unsigned& r3, unsigned addr) {
    asm volatile("ldmatrix.sync.aligned.m8n8.x4.trans.shared.b16 {%0,%1,%2,%3}, [%4];"
                 : "=r"(r0), "=r"(r1), "=r"(r2), "=r"(r3) : "r"(addr));
}

// ---------------------------------------------------------------------------
// fp32 -> fp16 convert (for x)
// ---------------------------------------------------------------------------
__global__ void cvt_f16_kernel(const float* __restrict__ in,
                               __half* __restrict__ out, size_t n4) {
    size_t i = (size_t)blockIdx.x * blockDim.x + threadIdx.x;
    size_t stride = (size_t)gridDim.x * blockDim.x;
    for (; i < n4; i += stride) {
        float4 v = ((const float4*)in)[i];
        __half2 a(__float2half_rn(v.x), __float2half_rn(v.y));
        __half2 b(__float2half_rn(v.z), __float2half_rn(v.w));
        ((__half2*)out)[i * 2]     = a;
        ((__half2*)out)[i * 2 + 1] = b;
    }
}

// ---------------------------------------------------------------------------
// Transpose + fp16 split: W[K][N] fp32 -> Wt hi (and optionally lo) [N][K]
// ---------------------------------------------------------------------------
__global__ void tsplit_f16_kernel(const float* __restrict__ W,
                                  __half* __restrict__ th,
                                  __half* __restrict__ tl, int K, int N) {
    __shared__ float t[32][33];
    int n0 = blockIdx.x * 32, k0 = blockIdx.y * 32;
    int tx = threadIdx.x, ty = threadIdx.y;           // (32, 8)
    #pragma unroll
    for (int i = ty; i < 32; i += 8)
        t[i][tx] = W[(size_t)(k0 + i) * N + n0 + tx];
    __syncthreads();
    #pragma unroll
    for (int i = ty; i < 32; i += 8) {
        float v = t[tx][i];
        __half h, l;
        split_f16(v, h, l);
        th[(size_t)(n0 + i) * K + k0 + tx] = h;
        if (tl) tl[(size_t)(n0 + i) * K + k0 + tx] = l;
    }
}

// ---------------------------------------------------------------------------
// fp16 triple-buffered cp.async GEMM.
// FUSED=1 (QKV): q/k use W hi+lo + rmsnorm/split epilogue; v uses W hi only
//                and a direct split/store epilogue ([row][Dn], no transpose).
// FUSED=0 (O-proj): single-term, plain bias + fp32 store.
// ---------------------------------------------------------------------------
#define BKK 32
#define PITCH 20                       // 16 data u32 + 4 pad (5x16B, coprime 8)
#define TILE_U32 (128 * PITCH)
#define TILEB (TILE_U32 * 4)
#define STAGE_U32 (3 * TILE_U32)       // A, Bh, Bl
#define GEMM_SMEM (3 * STAGE_U32 * 4)  // 92160 B

template<int FUSED>
__global__ __launch_bounds__(256, 2)
void gemm_f16x2(const __half* __restrict__ A,
                const __half* __restrict__ Bth,
                const __half* __restrict__ Btl,
                const float* __restrict__ bias,
                float* __restrict__ C,
                const float* __restrict__ wq,
                const float* __restrict__ wk,
                int Nz, int Kz) {
    extern __shared__ unsigned sm[];

    const int tid  = threadIdx.x;
    const int lane = tid & 31;
    const int wid  = tid >> 5;
    const int wm   = wid >> 2;
    const int wn   = wid & 3;
    const int g    = lane >> 2;
    const int tig  = lane & 3;
    const int lane8 = lane & 7;
    const int lb3  = (lane >> 3) & 1;
    const int lb4  = (lane >> 4) & 1;

    const int rowBase = blockIdx.y * 128;
    const int colBase = blockIdx.x * 128;
    const bool use_lo = FUSED ? (colBase < 2048) : false;

    const int r0 = tid >> 2;
    const int c4 = tid & 3;

    const unsigned smem_base = (unsigned)__cvta_generic_to_shared(sm);

    const unsigned a_off = (unsigned)((wm * 64 + lane8 + lb3 * 8) * 80 + lb4 * 16);
    const unsigned b_off = (unsigned)((wn * 32 + lane8 + lb4 * 8) * 80 + lb3 * 16);

    float acc[4][4][4];
    #pragma unroll
    for (int i = 0; i < 4; i++)
        #pragma unroll
        for (int j = 0; j < 4; j++)
            #pragma unroll
            for (int q = 0; q < 4; q++) acc[i][j][q] = 0.0f;

    const int NIT = Kz / BKK;

    auto load_stage = [&](int it, int buf) {
        const int k0 = it * BKK;
        const unsigned sbase = smem_base + buf * STAGE_U32 * 4;
        #pragma unroll
        for (int it2 = 0; it2 < 2; it2++) {
            int row = r0 + it2 * 64;
            unsigned soff = (unsigned)(row * PITCH + c4 * 4) * 4;
            const __half* gA  = A   + (size_t)(rowBase + row) * Kz + k0 + c4 * 8;
            const __half* gBh = Bth + (size_t)(colBase + row) * Kz + k0 + c4 * 8;
            cp16(sbase + soff, gA);
            cp16(sbase + TILEB + soff, gBh);
            if (use_lo) {
                const __half* gBl = Btl + (size_t)(colBase + row) * Kz + k0 + c4 * 8;
                cp16(sbase + 2 * TILEB + soff, gBl);
            }
        }
        asm volatile("cp.async.commit_group;");
    };

    load_stage(0, 0);
    load_stage(1, 1);

    for (int it = 0; it < NIT; it++) {
        const int buf = it % 3;
        if (it + 2 < NIT) {
            load_stage(it + 2, (it + 2) % 3);
            asm volatile("cp.async.wait_group 2;");
        } else if (it + 1 < NIT) {
            asm volatile("cp.async.wait_group 1;");
        } else {
            asm volatile("cp.async.wait_group 0;");
        }
        __syncthreads();

        const unsigned stg = smem_base + buf * STAGE_U32 * 4;

        #pragma unroll
        for (int kk8 = 0; kk8 < 2; kk8++) {
            unsigned a[4][4], bhi[4][2], blo[4][2];
            #pragma unroll
            for (int mi = 0; mi < 4; mi++) {
                unsigned ad = stg + a_off + (unsigned)(mi * 16 * 80 + kk8 * 32);
                ldsm4(a[mi][0], a[mi][1], a[mi][2], a[mi][3], ad);
            }
            #pragma unroll
            for (int p = 0; p < 2; p++) {
                unsigned bd = stg + TILEB + b_off + (unsigned)(p * 16 * 80 + kk8 * 32);
                ldsm4(bhi[2*p][0], bhi[2*p][1], bhi[2*p+1][0], bhi[2*p+1][1], bd);
            }
            if (use_lo) {
                #pragma unroll
                for (int p = 0; p < 2; p++) {
                    unsigned bd = stg + 2 * TILEB + b_off + (unsigned)(p * 16 * 80 + kk8 * 32);
                    ldsm4(blo[2*p][0], blo[2*p][1], blo[2*p+1][0], blo[2*p+1][1], bd);
                }
            }
            #pragma unroll
            for (int mi = 0; mi < 4; mi++)
                #pragma unroll
                for (int ni = 0; ni < 4; ni++) {
                    mma16816h(acc[mi][ni], a[mi], bhi[ni]);
                    if (use_lo) mma16816h(acc[mi][ni], a[mi], blo[ni]);
                }
        }
        __syncthreads();
    }

    if (!FUSED) {
        #pragma unroll
        for (int mi = 0; mi < 4; mi++) {
            int row0 = rowBase + wm * 64 + mi * 16 + g;
            int row1 = row0 + 8;
            #pragma unroll
            for (int ni = 0; ni < 4; ni++) {
                int col = colBase + wn * 32 + ni * 8 + tig * 2;
                float b0 = __ldg(&bias[col]);
                float b1 = __ldg(&bias[col + 1]);
                C[(size_t)row0 * Nz + col]     = acc[mi][ni][0] + b0;
                C[(size_t)row0 * Nz + col + 1] = acc[mi][ni][1] + b1;
                C[(size_t)row1 * Nz + col]     = acc[mi][ni][2] + b0;
                C[(size_t)row1 * Nz + col + 1] = acc[mi][ni][3] + b1;
            }
        }
        return;
    }

    // ----- FUSED epilogue (QKV) -----
    #pragma unroll
    for (int ni = 0; ni < 4; ni++) {
        int col = colBase + wn * 32 + ni * 8 + tig * 2;
        float b0 = __ldg(&bias[col]);
        float b1 = __ldg(&bias[col + 1]);
        #pragma unroll
        for (int mi = 0; mi < 4; mi++) {
            acc[mi][ni][0] += b0; acc[mi][ni][1] += b1;
            acc[mi][ni][2] += b0; acc[mi][ni][3] += b1;
        }
    }

    const int sec = colBase >> 10;         // 0=q, 1=k, 2=v
    const int cb  = colBase & 1023;
    const int head = (cb >> 6) + (wn >> 1);

    if (sec < 2) {
        // --- RMSNorm + fp16 split for q/k ---
        float* red = (float*)sm;
        #pragma unroll
        for (int mi = 0; mi < 4; mi++) {
            float l0 = 0.0f, l1 = 0.0f;
            #pragma unroll
            for (int ni = 0; ni < 4; ni++) {
                l0 += acc[mi][ni][0] * acc[mi][ni][0] + acc[mi][ni][1] * acc[mi][ni][1];
                l1 += acc[mi][ni][2] * acc[mi][ni][2] + acc[mi][ni][3] * acc[mi][ni][3];
            }
            l0 += __shfl_xor_sync(0xffffffffu, l0, 1);
            l0 += __shfl_xor_sync(0xffffffffu, l0, 2);
            l1 += __shfl_xor_sync(0xffffffffu, l1, 1);
            l1 += __shfl_xor_sync(0xffffffffu, l1, 2);
            if (tig == 0) {
                int lr = wm * 64 + mi * 16 + g;
                red[wn * 128 + lr]     = l0;
                red[wn * 128 + lr + 8] = l1;
            }
        }
        __syncthreads();

        const float* wv = sec ? wk : wq;
        __half* dh = sec ? g_Kh : g_Qh;
        __half* dl = sec ? g_Kl : g_Ql;

        #pragma unroll
        for (int mi = 0; mi < 4; mi++) {
            int lr = wm * 64 + mi * 16 + g;
            float ssq0 = red[wn * 128 + lr]     + red[(wn ^ 1) * 128 + lr];
            float ssq1 = red[wn * 128 + lr + 8] + red[(wn ^ 1) * 128 + lr + 8];
            float inv0 = rsqrtf(ssq0 * (1.0f / DH) + 1e-6f);
            float inv1 = rsqrtf(ssq1 * (1.0f / DH) + 1e-6f);
            size_t row0 = (size_t)(rowBase + lr);
            size_t row1 = row0 + 8;
            #pragma unroll
            for (int ni = 0; ni < 4; ni++) {
                int ic = (wn & 1) * 32 + ni * 8 + tig * 2;
                float wf0 = __ldg(&wv[ic]);
                float wf1 = __ldg(&wv[ic + 1]);
                size_t o0 = row0 * Dn + head * 64 + ic;
                size_t o1 = row1 * Dn + head * 64 + ic;
                __half h0, lo0, h1, lo1;
                split_f16(acc[mi][ni][0] * inv0 * wf0, h0, lo0);
                split_f16(acc[mi][ni][1] * inv0 * wf1, h1, lo1);
                *(unsigned*)&dh[o0] = pack2h(h0, h1);
                *(unsigned*)&dl[o0] = pack2h(lo0, lo1);
                split_f16(acc[mi][ni][2] * inv1 * wf0, h0, lo0);
                split_f16(acc[mi][ni][3] * inv1 * wf1, h1, lo1);
                *(unsigned*)&dh[o1] = pack2h(h0, h1);
                *(unsigned*)&dl[o1] = pack2h(lo0, lo1);
            }
        }
    } else {
        // --- V: direct split + store in [row][Dn] (no transpose needed) ---
        #pragma unroll
        for (int mi = 0; mi < 4; mi++) {
            int lr = wm * 64 + mi * 16 + g;
            size_t row0 = (size_t)(rowBase + lr);
            size_t row1 = row0 + 8;
            #pragma unroll
            for (int ni = 0; ni < 4; ni++) {
                int ic = (wn & 1) * 32 + ni * 8 + tig * 2;
                size_t o0 = row0 * Dn + head * 64 + ic;
                size_t o1 = row1 * Dn + head * 64 + ic;
                __half h0, lo0, h1, lo1;
                split_f16(acc[mi][ni][0], h0, lo0);
                split_f16(acc[mi][ni][1], h1, lo1);
                *(unsigned*)&g_Vh[o0] = pack2h(h0, h1);
                *(unsigned*)&g_Vl[o0] = pack2h(lo0, lo1);
                split_f16(acc[mi][ni][2], h0, lo0);
                split_f16(acc[mi][ni][3], h1, lo1);
                *(unsigned*)&g_Vh[o1] = pack2h(h0, h1);
                *(unsigned*)&g_Vl[o1] = pack2h(lo0, lo1);
            }
        }
    }
}

// ---------------------------------------------------------------------------
// Flash attention: Q fragments in registers, cp.async double-buffered K/V.
// QK^T fp16x3; PV fp16 P x fp16 hi/lo V with V fragments loaded via
// ldmatrix.trans from [s][d]-layout tiles (value-identical to the old Vt path).
// Smem: 2 stages x (Kh,Kl,Vh,Vl) = 8 ATILE = 73728 B; 3 CTAs/SM.
// ---------------------------------------------------------------------------
#define AP 36
#define ATILE (64 * AP)
#define ATB (ATILE * 4)                // tile bytes 9216
#define ATTN_SMEM (8 * ATILE * 4)      // 73728 B

__global__ __launch_bounds__(128, 3) void attn_mma_kernel() {
    extern __shared__ unsigned smu[];

    const int tid  = threadIdx.x;
    const int lane = tid & 31;
    const int w    = tid >> 5;
    const int g    = lane >> 2;
    const int tig  = lane & 3;
    const int lane8 = lane & 7;
    const int lb3  = (lane >> 3) & 1;
    const int lb4  = (lane >> 4) & 1;

    const int qt = gridDim.x - 1 - blockIdx.x;
    const int h  = blockIdx.y;
    const int b  = blockIdx.z;

    const size_t rowQ0 = (size_t)b * Sn + qt * 64;
    const size_t qk_off = h * DH;

    const unsigned smu_b = (unsigned)__cvta_generic_to_shared(smu);
    const int m0r = w * 16;
    const unsigned q_loff = (unsigned)((m0r + lane8 + lb3 * 8) * 144 + lb4 * 16);
    const unsigned n_loff = (unsigned)((lane8 + lb4 * 8) * 144 + lb3 * 16);
    // V (trans) per-lane offset: rows = k (s), cols = d
    const unsigned v_loff = (unsigned)((lane8 + lb3 * 8) * 144 + lb4 * 16);

    // ---- Stage Q into stage-0 area, extract fragments to registers ----
    #pragma unroll
    for (int it = 0; it < 4; it++) {
        int idx = tid + it * 128;
        int r = idx >> 3, q4 = idx & 7;
        const uint4* gh = (const uint4*)(g_Qh + (rowQ0 + r) * Dn + qk_off);
        const uint4* gl = (const uint4*)(g_Ql + (rowQ0 + r) * Dn + qk_off);
        ((uint4*)(smu + r * AP))[q4] = gh[q4];
        ((uint4*)(smu + ATILE + r * AP))[q4] = gl[q4];
    }
    __syncthreads();
    unsigned qah[4][4], qal[4][4];
    #pragma unroll
    for (int kk = 0; kk < 4; kk++) {
        ldsm4(qah[kk][0], qah[kk][1], qah[kk][2], qah[kk][3],
              smu_b + q_loff + kk * 32);
        ldsm4(qal[kk][0], qal[kk][1], qal[kk][2], qal[kk][3],
              smu_b + ATB + q_loff + kk * 32);
    }
    __syncthreads();

    float o[8][4];
    #pragma unroll
    for (int ni = 0; ni < 8; ni++)
        #pragma unroll
        for (int c = 0; c < 4; c++) o[ni][c] = 0.0f;
    float m0 = -INFINITY, m1 = -INFINITY, lp0 = 0.0f, lp1 = 0.0f;

    // K/V pipeline: stage s base = s * 4 * ATB; tiles Kh,Kl,Vh,Vl (all [s][d])
    auto load_kv = [&](int kt, int s) {
        const size_t rowK0 = (size_t)b * Sn + kt * 64;
        const unsigned sb = smu_b + (unsigned)(s * 4 * ATB);
        #pragma unroll
        for (int it = 0; it < 4; it++) {
            int idx = tid + it * 128;
            int r = idx >> 3, q4 = idx & 7;
            unsigned soff = (unsigned)(r * 144 + q4 * 16);
            cp16(sb + soff,           g_Kh + (rowK0 + r) * Dn + qk_off + q4 * 8);
            cp16(sb + ATB + soff,     g_Kl + (rowK0 + r) * Dn + qk_off + q4 * 8);
            cp16(sb + 2 * ATB + soff, g_Vh + (rowK0 + r) * Dn + qk_off + q4 * 8);
            cp16(sb + 3 * ATB + soff, g_Vl + (rowK0 + r) * Dn + qk_off + q4 * 8);
        }
        asm volatile("cp.async.commit_group;");
    };

    load_kv(0, 0);

    for (int kt = 0; kt <= qt; kt++) {
        const int s = kt & 1;
        if (kt < qt) {
            load_kv(kt + 1, s ^ 1);
            asm volatile("cp.async.wait_group 1;");
        } else {
            asm volatile("cp.async.wait_group 0;");
        }
        __syncthreads();

        const unsigned kvb = smu_b + (unsigned)(s * 4 * ATB);

        float sc[8][4];
        #pragma unroll
        for (int ni = 0; ni < 8; ni++)
            #pragma unroll
            for (int c = 0; c < 4; c++) sc[ni][c] = 0.0f;

        #pragma unroll
        for (int kk = 0; kk < 4; kk++) {
            #pragma unroll
            for (int p = 0; p < 4; p++) {
                unsigned bh[4], bl[4];
                unsigned kd = kvb + n_loff + (unsigned)(p * 16 * 144 + kk * 32);
                ldsm4(bh[0], bh[1], bh[2], bh[3], kd);
                ldsm4(bl[0], bl[1], bl[2], bl[3], kd + ATB);
                mma16816h(sc[2*p],   qah[kk], bh);
                mma16816h(sc[2*p],   qah[kk], bl);
                mma16816h(sc[2*p],   qal[kk], bh);
                mma16816h(sc[2*p+1], qah[kk], bh + 2);
                mma16816h(sc[2*p+1], qah[kk], bl + 2);
                mma16816h(sc[2*p+1], qal[kk], bh + 2);
            }
        }

        if (kt == qt) {
            #pragma unroll
            for (int ni = 0; ni < 8; ni++) {
                int col = ni * 8 + 2 * tig;
                int r0 = m0r + g, r1 = r0 + 8;
                if (col > r0)     sc[ni][0] = -INFINITY;
                if (col + 1 > r0) sc[ni][1] = -INFINITY;
                if (col > r1)     sc[ni][2] = -INFINITY;
                if (col + 1 > r1) sc[ni][3] = -INFINITY;
            }
        }

        float rm0 = -INFINITY, rm1 = -INFINITY;
        #pragma unroll
        for (int ni = 0; ni < 8; ni++) {
            rm0 = fmaxf(rm0, fmaxf(sc[ni][0], sc[ni][1]));
            rm1 = fmaxf(rm1, fmaxf(sc[ni][2], sc[ni][3]));
        }
        rm0 = fmaxf(rm0, __shfl_xor_sync(0xffffffffu, rm0, 1));
        rm0 = fmaxf(rm0, __shfl_xor_sync(0xffffffffu, rm0, 2));
        rm1 = fmaxf(rm1, __shfl_xor_sync(0xffffffffu, rm1, 1));
        rm1 = fmaxf(rm1, __shfl_xor_sync(0xffffffffu, rm1, 2));
        float mn0 = fmaxf(m0, rm0), mn1 = fmaxf(m1, rm1);

        float rs0 = 0.0f, rs1 = 0.0f;
        #pragma unroll
        for (int ni = 0; ni < 8; ni++) {
            sc[ni][0] = __expf(sc[ni][0] - mn0);
            sc[ni][1] = __expf(sc[ni][1] - mn0);
            sc[ni][2] = __expf(sc[ni][2] - mn1);
            sc[ni][3] = __expf(sc[ni][3] - mn1);
            rs0 += sc[ni][0] + sc[ni][1];
            rs1 += sc[ni][2] + sc[ni][3];
        }

        float al0 = __expf(m0 - mn0), al1 = __expf(m1 - mn1);
        lp0 = lp0 * al0 + rs0;
        lp1 = lp1 * al1 + rs1;
        m0 = mn0; m1 = mn1;
        #pragma unroll
        for (int ni = 0; ni < 8; ni++) {
            o[ni][0] *= al0; o[ni][1] *= al0;
            o[ni][2] *= al1; o[ni][3] *= al1;
        }

        // ---- O += P @ V : V fragments via ldmatrix.trans from [s][d] ----
        #pragma unroll
        for (int kk = 0; kk < 4; kk++) {
            unsigned pah[4];
            {
                __half2 p0(__float2half_rn(sc[2*kk][0]),   __float2half_rn(sc[2*kk][1]));
                __half2 p1(__float2half_rn(sc[2*kk][2]),   __float2half_rn(sc[2*kk][3]));
                __half2 p2(__float2half_rn(sc[2*kk+1][0]), __float2half_rn(sc[2*kk+1][1]));
                __half2 p3(__float2half_rn(sc[2*kk+1][2]), __float2half_rn(sc[2*kk+1][3]));
                pah[0] = *(unsigned*)&p0;
                pah[1] = *(unsigned*)&p1;
                pah[2] = *(unsigned*)&p2;
                pah[3] = *(unsigned*)&p3;
            }
            #pragma unroll
            for (int p = 0; p < 4; p++) {
                unsigned vh[4], vl[4];
                unsigned vd = kvb + 2 * ATB + v_loff + (unsigned)(kk * 16 * 144 + p * 32);
                ldsm4t(vh[0], vh[1], vh[2], vh[3], vd);
                ldsm4t(vl[0], vl[1], vl[2], vl[3], vd + ATB);
                mma16816h(o[2*p],   pah, vh);
                mma16816h(o[2*p],   pah, vl);
                mma16816h(o[2*p+1], pah, vh + 2);
                mma16816h(o[2*p+1], pah, vl + 2);
            }
        }
        __syncthreads();
    }

    lp0 += __shfl_xor_sync(0xffffffffu, lp0, 1);
    lp0 += __shfl_xor_sync(0xffffffffu, lp0, 2);
    lp1 += __shfl_xor_sync(0xffffffffu, lp1, 1);
    lp1 += __shfl_xor_sync(0xffffffffu, lp1, 2);

    float inv0 = 1.0f / lp0, inv1 = 1.0f / lp1;
    size_t row0 = rowQ0 + w * 16 + g;
    size_t row1 = row0 + 8;
    #pragma unroll
    for (int ni = 0; ni < 8; ni++) {
        int col = h * DH + ni * 8 + 2 * tig;
        __half2 z0(__float2half_rn(o[ni][0] * inv0), __float2half_rn(o[ni][1] * inv0));
        __half2 z1(__float2half_rn(o[ni][2] * inv1), __float2half_rn(o[ni][3] * inv1));
        *(__half2*)&g_Ah[row0 * Dn + col] = z0;
        *(__half2*)&g_Ah[row1 * Dn + col] = z1;
    }
}

// ---------------------------------------------------------------------------
extern "C" void kernel_launch(void* const* d_in, const int* in_sizes, int n_in,
                              void* d_out, int out_size) {
    const float* x     = (const float*)d_in[0];
    const float* W_qkv = (const float*)d_in[2];
    const float* b_qkv = (const float*)d_in[3];
    const float* W_o   = (const float*)d_in[4];
    const float* b_o   = (const float*)d_in[5];
    const float* wq    = (const float*)d_in[6];
    const float* wk    = (const float*)d_in[7];
    float* out = (float*)d_out;

    void *ah, *wth, *wtl, *woth;
    cudaGetSymbolAddress(&ah, g_Ah);
    cudaGetSymbolAddress(&wth, g_Wth);
    cudaGetSymbolAddress(&wtl, g_Wtl);
    cudaGetSymbolAddress(&woth, g_Woth);

    cudaFuncSetAttribute(gemm_f16x2<1>,
                         cudaFuncAttributeMaxDynamicSharedMemorySize, GEMM_SMEM);
    cudaFuncSetAttribute(gemm_f16x2<0>,
                         cudaFuncAttributeMaxDynamicSharedMemorySize, GEMM_SMEM);
    cudaFuncSetAttribute(attn_mma_kernel,
                         cudaFuncAttributeMaxDynamicSharedMemorySize, ATTN_SMEM);

    // 0) Preprocessing: x -> fp16; W_qkv -> hi/lo transpose; W_o -> hi only
    cvt_f16_kernel<<<1024, 256>>>(x, (__half*)ah, (size_t)Mrows * Dn / 4);
    {
        dim3 grid(N3 / 32, Dn / 32);
        tsplit_f16_kernel<<<grid, dim3(32, 8)>>>(W_qkv, (__half*)wth,
                                                 (__half*)wtl, Dn, N3);
    }
    {
        dim3 grid(Dn / 32, Dn / 32);
        tsplit_f16_kernel<<<grid, dim3(32, 8)>>>(W_o, (__half*)woth,
                                                 nullptr, Dn, Dn);
    }

    // 1) QKV GEMM (fp16x2 on q/k, fp16 on v) + fused rmsnorm / v-split
    {
        dim3 grid(N3 / 128, Mrows / 128);
        gemm_f16x2<1><<<grid, 256, GEMM_SMEM>>>(
            (const __half*)ah, (const __half*)wth, (const __half*)wtl,
            b_qkv, nullptr, wq, wk, N3, Dn);
    }

    // 2) Flash attention (Q-in-regs, cp.async K/V pipeline, trans-V)
    {
        dim3 grid(Sn / 64, NH, Bn);
        attn_mma_kernel<<<grid, 128, ATTN_SMEM>>>();
    }

    // 3) Output projection (single-term fp16 W)
    {
        dim3 grid(Dn / 128, Mrows / 128);
        gemm_f16x2<0><<<grid, 256, GEMM_SMEM>>>(
            (const __half*)ah, (const __half*)woth, nullptr,
            b_o, out, nullptr, nullptr, Dn, Dn);
    }
}